// round 1
// baseline (speedup 1.0000x reference)
#include <cuda_runtime.h>
#include <math.h>

#define G   4096
#define NN  64
#define EE  256
#define FF  64
#define DD  128
#define EPN 32768

// ---------------- device scratch (static, no allocations) ----------------
__device__ float d_gembs[G * DD];     // graph embeddings
__device__ float d_deg[G];            // graph-level degree -> dinv
__device__ float d_agg1[G * DD];      // aggregated g_embs
__device__ float d_h[G * 2 * DD];     // relu(conv1)
__device__ float d_agg2[G * 2 * DD];  // aggregated h
__device__ float d_mu[G * DD];
__device__ float d_ls[G * DD];
__device__ float d_zc[G * 2 * DD];    // [emb | z]
__device__ float d_zl1[G * 2 * DD];
__device__ float d_zl2[G * 2 * DD];
__device__ float d_sums[8];           // 0:pen 1:plog 2:nlog 3:kl

// ---------------- zero scratch accumulators ----------------
__global__ void k_zero() {
    int i = blockIdx.x * blockDim.x + threadIdx.x;
    int stride = gridDim.x * blockDim.x;
    for (int j = i; j < G * 2 * DD; j += stride) d_agg2[j] = 0.f;
    for (int j = i; j < G * DD; j += stride) d_agg1[j] = 0.f;
    for (int j = i; j < G; j += stride) d_deg[j] = 0.f;
    if (i < 8) d_sums[i] = 0.f;
}

// ---------------- per-graph kernel: GCN + pooling head ----------------
// One block per graph, 128 threads; thread t owns output channel t.
// dynamic smem: sx[64*64] | sxw[64*128] | sagg/h[64*128]  = 80KB
__global__ void __launch_bounds__(128) k_graph(
    const float* __restrict__ x, const int* __restrict__ ei, const float* __restrict__ ew,
    const float* __restrict__ Wg, const float* __restrict__ bg,
    const float* __restrict__ Wf1, const float* __restrict__ bf1,
    const float* __restrict__ Wf2, const float* __restrict__ bf2)
{
    extern __shared__ float sm[];
    float* sx  = sm;                 // 4096 floats
    float* sxw = sm + 4096;          // 8192 floats
    float* sh  = sm + 12288;         // 8192 floats (agg, then h)

    __shared__ int   ssrc[EE], sdst[EE];
    __shared__ float swt[EE], snorm[EE], slw[EE];
    __shared__ float sdeg[NN], sdinv[NN], sdeg2[NN], sdinv2[NN];
    __shared__ float sS[NN * 2];
    __shared__ float sa1[NN * 16];
    __shared__ float sred[16];

    int g = blockIdx.x, t = threadIdx.x;

    // load x tile (64x64)
    const float4* xg = (const float4*)(x + (size_t)g * (NN * FF));
    float4* sx4 = (float4*)sx;
    for (int i = t; i < NN * FF / 4; i += 128) sx4[i] = xg[i];

    // load edges
    for (int e = t; e < EE; e += 128) {
        ssrc[e] = ei[(size_t)g * 2 * EE + e];
        sdst[e] = ei[(size_t)g * 2 * EE + EE + e];
        swt[e]  = ew[(size_t)g * EE + e];
    }
    if (t < NN) { sdeg[t] = 0.f; sdeg2[t] = 0.f; }
    __syncthreads();

    for (int e = t; e < EE; e += 128) {
        atomicAdd(&sdeg[sdst[e]], swt[e]);    // gcn deg (at dst)
        atomicAdd(&sdeg2[ssrc[e]], swt[e]);   // laplacian deg (at src)
    }
    __syncthreads();

    if (t < NN) {
        sdinv[t] = rsqrtf(sdeg[t] + 1.0f);
        float d2 = sdeg2[t];
        sdinv2[t] = (d2 > 0.f) ? rsqrtf(fmaxf(d2, 1e-30f)) : 0.f;
    }
    __syncthreads();

    for (int e = t; e < EE; e += 128) {
        int s_ = ssrc[e], dd = sdst[e];
        snorm[e] = sdinv[s_] * swt[e] * sdinv[dd];
        slw[e]   = -sdinv2[s_] * swt[e] * sdinv2[dd];
    }

    // xw = x @ W_gcn1  — thread t owns column t, acc over 64 nodes in regs
    float acc[NN];
#pragma unroll
    for (int n = 0; n < NN; n++) acc[n] = 0.f;
    for (int k = 0; k < FF; k += 4) {
        float w0 = Wg[(k + 0) * DD + t];
        float w1 = Wg[(k + 1) * DD + t];
        float w2 = Wg[(k + 2) * DD + t];
        float w3 = Wg[(k + 3) * DD + t];
#pragma unroll
        for (int n = 0; n < NN; n++) {
            float4 xv = *(const float4*)&sx[n * FF + k];
            acc[n] += xv.x * w0 + xv.y * w1 + xv.z * w2 + xv.w * w3;
        }
    }
#pragma unroll
    for (int n = 0; n < NN; n++) sxw[n * DD + t] = acc[n];
    for (int i = t; i < NN * DD; i += 128) sh[i] = 0.f;
    __syncthreads();

    // scatter (column-owned -> race-free, no atomics)
    for (int e = 0; e < EE; e++)
        sh[sdst[e] * DD + t] += sxw[ssrc[e] * DD + t] * snorm[e];

    // h = agg + xw*dinv^2 + b  (in place, own column only)
    float bias_t = bg[t];
#pragma unroll
    for (int n = 0; n < NN; n++) {
        float di = sdinv[n];
        sh[n * DD + t] = sh[n * DD + t] + acc[n] * di * di + bias_t;
    }
    __syncthreads();

    // a1 = tanh(h @ Wf1 + bf1) : 64x16
    for (int o = t; o < NN * 16; o += 128) {
        int n = o >> 4, j = o & 15;
        float s = bf1[j];
        for (int d = 0; d < DD; d++) s += sh[n * DD + d] * Wf1[d * 16 + j];
        sa1[o] = tanhf(s);
    }
    __syncthreads();

    // S = softmax(a1 @ Wf2 + bf2) : 64x2
    if (t < NN) {
        float l0 = bf2[0], l1 = bf2[1];
#pragma unroll
        for (int j = 0; j < 16; j++) {
            float a = sa1[t * 16 + j];
            l0 += a * Wf2[j * 2]; l1 += a * Wf2[j * 2 + 1];
        }
        float m = fmaxf(l0, l1);
        float e0 = expf(l0 - m), e1 = expf(l1 - m);
        float inv = 1.f / (e0 + e1);
        sS[t * 2] = e0 * inv; sS[t * 2 + 1] = e1 * inv;
    }
    __syncthreads();

    // new_adj = S^T S + sum_e lw * S[src]^T outer S[dst]
    float a00 = 0, a01 = 0, a10 = 0, a11 = 0;
    for (int n = t; n < NN; n += 128) {
        float s0 = sS[n * 2], s1 = sS[n * 2 + 1];
        a00 += s0 * s0; a01 += s0 * s1; a10 += s1 * s0; a11 += s1 * s1;
    }
    for (int e = t; e < EE; e += 128) {
        float lw = slw[e];
        int s_ = ssrc[e], dd = sdst[e];
        float p0 = sS[s_ * 2], p1 = sS[s_ * 2 + 1];
        float q0 = sS[dd * 2], q1 = sS[dd * 2 + 1];
        a00 += lw * p0 * q0; a01 += lw * p0 * q1;
        a10 += lw * p1 * q0; a11 += lw * p1 * q1;
    }
    for (int off = 16; off; off >>= 1) {
        a00 += __shfl_down_sync(0xffffffffu, a00, off);
        a01 += __shfl_down_sync(0xffffffffu, a01, off);
        a10 += __shfl_down_sync(0xffffffffu, a10, off);
        a11 += __shfl_down_sync(0xffffffffu, a11, off);
    }
    if ((t & 31) == 0) {
        int w = t >> 5;
        sred[w * 4 + 0] = a00; sred[w * 4 + 1] = a01;
        sred[w * 4 + 2] = a10; sred[w * 4 + 3] = a11;
    }
    __syncthreads();
    if (t == 0) {
        float A00 = 0, A01 = 0, A10 = 0, A11 = 0;
        for (int w = 0; w < 4; w++) {
            A00 += sred[w * 4 + 0]; A01 += sred[w * 4 + 1];
            A10 += sred[w * 4 + 2]; A11 += sred[w * 4 + 3];
        }
        float r0 = fmaxf(fabsf(A00) + fabsf(A01), 1e-12f);
        float r1 = fmaxf(fabsf(A10) + fabsf(A11), 1e-12f);
        float d0 = A00 / r0 - 1.f, d1 = A11 / r1 - 1.f;
        atomicAdd(&d_sums[0], 0.5f * (d0 * d0 + d1 * d1));
    }

    // g_emb = 0.5 * sum_n h[n]  (softmax rows sum to 1 -> S drops out)
    float s = 0.f;
#pragma unroll
    for (int n = 0; n < NN; n++) s += sh[n * DD + t];
    d_gembs[(size_t)g * DD + t] = 0.5f * s;
}

// ---------------- graph-level degree ----------------
__global__ void k_deg(const int* __restrict__ pe) {
    int i = blockIdx.x * blockDim.x + threadIdx.x;
    if (i < EPN) atomicAdd(&d_deg[pe[EPN + i]], 1.0f);
}
__global__ void k_dinv() {
    int i = blockIdx.x * blockDim.x + threadIdx.x;
    if (i < G) d_deg[i] = rsqrtf(d_deg[i] + 1.0f);  // deg + self-loop
}

// ---------------- scatter: warp per edge ----------------
__global__ void __launch_bounds__(256) k_scatter(const int* __restrict__ pe, int sel) {
    int gw = (blockIdx.x * 256 + threadIdx.x) >> 5;
    int lane = threadIdx.x & 31;
    if (gw >= EPN) return;
    int a = pe[gw], b = pe[EPN + gw];
    float norm = d_deg[a] * d_deg[b];
    if (sel == 0) {
        const float* X = d_gembs + (size_t)a * DD;
        float* Ag = d_agg1 + (size_t)b * DD;
#pragma unroll
        for (int d = lane; d < DD; d += 32) atomicAdd(&Ag[d], X[d] * norm);
    } else {
        const float* X = d_h + (size_t)a * 256;
        float* Ag = d_agg2 + (size_t)b * 256;
#pragma unroll
        for (int d = lane; d < 256; d += 32) atomicAdd(&Ag[d], X[d] * norm);
    }
}
__global__ void k_self(int sel) {
    int i = blockIdx.x * blockDim.x + threadIdx.x;
    if (sel == 0) {
        float di = d_deg[i >> 7];
        d_agg1[i] += d_gembs[i] * di * di;
    } else {
        float di = d_deg[i >> 8];
        d_agg2[i] += d_h[i] * di * di;
    }
}

// ---------------- generic tiled GEMM: C = act(A @ W + b) ----------------
// M = 4096 always. sel_in: 0 agg1(K=128) 1 agg2(K=256) 2 zc(K=256)
// sel_out: 0 h, 1 mu, 2 ls, 3 zl1, 4 zl2. act: 0 none, 1 relu, 2 min(.,10)
__global__ void __launch_bounds__(256) k_gemm(int sel_in, int sel_out,
    const float* __restrict__ W, const float* __restrict__ bias,
    int N, int K, int act)
{
    const float* A = (sel_in == 0) ? d_agg1 : (sel_in == 1) ? d_agg2 : d_zc;
    float* C = (sel_out == 0) ? d_h : (sel_out == 1) ? d_mu : (sel_out == 2) ? d_ls
             : (sel_out == 3) ? d_zl1 : d_zl2;

    __shared__ float As[16][68];
    __shared__ float Bs[16][68];
    int tid = threadIdx.x;
    int tx = tid & 15, ty = tid >> 4;
    int rowBase = blockIdx.y * 64;
    int colBase = blockIdx.x * 64;
    float acc[4][4];
#pragma unroll
    for (int i = 0; i < 4; i++)
#pragma unroll
        for (int j = 0; j < 4; j++) acc[i][j] = 0.f;

    int lm = tid >> 2, lk = (tid & 3) << 2;
    int lk2 = tid >> 4, ln = (tid & 15) << 2;
    for (int k0 = 0; k0 < K; k0 += 16) {
        float4 av = *(const float4*)&A[(size_t)(rowBase + lm) * K + k0 + lk];
        As[lk + 0][lm] = av.x; As[lk + 1][lm] = av.y;
        As[lk + 2][lm] = av.z; As[lk + 3][lm] = av.w;
        float4 wv = *(const float4*)&W[(size_t)(k0 + lk2) * N + colBase + ln];
        Bs[lk2][ln + 0] = wv.x; Bs[lk2][ln + 1] = wv.y;
        Bs[lk2][ln + 2] = wv.z; Bs[lk2][ln + 3] = wv.w;
        __syncthreads();
#pragma unroll
        for (int kk = 0; kk < 16; kk++) {
            float4 a4 = *(const float4*)&As[kk][ty * 4];
            float4 b4 = *(const float4*)&Bs[kk][tx * 4];
            float avv[4] = {a4.x, a4.y, a4.z, a4.w};
            float bvv[4] = {b4.x, b4.y, b4.z, b4.w};
#pragma unroll
            for (int i = 0; i < 4; i++)
#pragma unroll
                for (int j = 0; j < 4; j++) acc[i][j] += avv[i] * bvv[j];
        }
        __syncthreads();
    }
#pragma unroll
    for (int i = 0; i < 4; i++) {
        int r = rowBase + ty * 4 + i;
#pragma unroll
        for (int j = 0; j < 4; j++) {
            int c = colBase + tx * 4 + j;
            float v = acc[i][j] + bias[c];
            if (act == 1) v = fmaxf(v, 0.f);
            else if (act == 2) v = fminf(v, 10.f);
            C[(size_t)r * N + c] = v;
        }
    }
}

// ---------------- z, zc, KL ----------------
__global__ void __launch_bounds__(256) k_z(const float* __restrict__ eps_,
                                           const float* __restrict__ emb) {
    int i = blockIdx.x * 256 + threadIdx.x;   // i < G*128 exactly
    float m = d_mu[i], l = d_ls[i];
    int n = i >> 7, d = i & 127;
    float z = m + eps_[i] * expf(l);
    d_zc[(size_t)n * 256 + d] = emb[i];
    d_zc[(size_t)n * 256 + 128 + d] = z;
    float klt = 1.f + 2.f * l - m * m - expf(2.f * l);
    for (int off = 16; off; off >>= 1) klt += __shfl_down_sync(0xffffffffu, klt, off);
    __shared__ float sw[8];
    if ((threadIdx.x & 31) == 0) sw[threadIdx.x >> 5] = klt;
    __syncthreads();
    if (threadIdx.x == 0) {
        float s = 0;
        for (int j = 0; j < 8; j++) s += sw[j];
        atomicAdd(&d_sums[3], s);
    }
}

// ---------------- edge predictions + log sums ----------------
__global__ void __launch_bounds__(256) k_pred(const int* __restrict__ pe,
                                              const int* __restrict__ ne,
                                              float* __restrict__ out) {
    int gw = (blockIdx.x * 256 + threadIdx.x) >> 5;   // 0..2*EP-1
    int lane = threadIdx.x & 31;
    int wib = threadIdx.x >> 5;
    bool isneg = gw >= EPN;
    int i = isneg ? gw - EPN : gw;
    const int* e = isneg ? ne : pe;
    int a = e[i], b = e[EPN + i];
    const float4* ra = (const float4*)(d_zl1 + (size_t)a * 256);
    const float4* rb = (const float4*)(d_zl2 + (size_t)b * 256);
    float s = 0.f;
#pragma unroll
    for (int q = 0; q < 2; q++) {
        float4 u = ra[lane + 32 * q], v = rb[lane + 32 * q];
        s += u.x * v.x + u.y * v.y + u.z * v.z + u.w * v.w;
    }
    for (int off = 16; off; off >>= 1) s += __shfl_down_sync(0xffffffffu, s, off);
    __shared__ float sl[8];
    if (lane == 0) {
        float p = 1.f / (1.f + expf(-s));
        out[2 + gw] = p;
        sl[wib] = isneg ? logf(1.f - p + 1e-15f) : logf(p + 1e-15f);
    }
    __syncthreads();
    if (threadIdx.x == 0) {
        float t = 0;
        for (int j = 0; j < 8; j++) t += sl[j];
        atomicAdd(isneg ? &d_sums[2] : &d_sums[1], t);
    }
}

__global__ void k_final(float* __restrict__ out) {
    float rec = -(d_sums[1] / (float)EPN) - (d_sums[2] / (float)EPN);
    float kl = -0.5f * d_sums[3] / (float)G;
    out[0] = rec + kl / (float)G;
    out[1] = d_sums[0] / (float)G;
}

// ---------------- launch ----------------
extern "C" void kernel_launch(void* const* d_in, const int* in_sizes, int n_in,
                              void* d_out, int out_size) {
    const float* x   = (const float*)d_in[0];
    const int*   ei  = (const int*)d_in[1];
    const float* ew  = (const float*)d_in[2];
    const int*   pe  = (const int*)d_in[3];
    const int*   ne  = (const int*)d_in[4];
    const float* eps_= (const float*)d_in[5];
    const float* Wg  = (const float*)d_in[6];
    const float* bg  = (const float*)d_in[7];
    const float* Wf1 = (const float*)d_in[8];
    const float* bf1 = (const float*)d_in[9];
    const float* Wf2 = (const float*)d_in[10];
    const float* bf2 = (const float*)d_in[11];
    const float* Wc1 = (const float*)d_in[12];
    const float* bc1 = (const float*)d_in[13];
    const float* Wmu = (const float*)d_in[14];
    const float* bmu = (const float*)d_in[15];
    const float* Wls = (const float*)d_in[16];
    const float* bls = (const float*)d_in[17];
    const float* emb = (const float*)d_in[18];
    const float* Wl1 = (const float*)d_in[19];
    const float* bl1 = (const float*)d_in[20];
    const float* Wl2 = (const float*)d_in[21];
    const float* bl2 = (const float*)d_in[22];
    float* out = (float*)d_out;

    // persistent per-function attribute; ignore return (persists from first call)
    cudaFuncSetAttribute(k_graph, cudaFuncAttributeMaxDynamicSharedMemorySize, 81920);

    k_zero<<<1024, 256>>>();
    k_graph<<<G, 128, 81920>>>(x, ei, ew, Wg, bg, Wf1, bf1, Wf2, bf2);
    k_deg<<<EPN / 256, 256>>>(pe);
    k_dinv<<<G / 256, 256>>>();
    k_scatter<<<EPN * 32 / 256, 256>>>(pe, 0);
    k_self<<<G * DD / 256, 256>>>(0);
    k_gemm<<<dim3(4, 64), 256>>>(0, 0, Wc1, bc1, 256, 128, 1);   // h = relu(conv1)
    k_scatter<<<EPN * 32 / 256, 256>>>(pe, 1);
    k_self<<<G * 256 / 256, 256>>>(1);
    k_gemm<<<dim3(2, 64), 256>>>(1, 1, Wmu, bmu, 128, 256, 0);   // mu
    k_gemm<<<dim3(2, 64), 256>>>(1, 2, Wls, bls, 128, 256, 2);   // logstd (min 10)
    k_z<<<G * DD / 256, 256>>>(eps_, emb);
    k_gemm<<<dim3(4, 64), 256>>>(2, 3, Wl1, bl1, 256, 256, 0);   // zl1
    k_gemm<<<dim3(4, 64), 256>>>(2, 4, Wl2, bl2, 256, 256, 0);   // zl2
    k_pred<<<2 * EPN * 32 / 256, 256>>>(pe, ne, out);
    k_final<<<1, 1>>>(out);
}

// round 2
// speedup vs baseline: 1.3836x; 1.3836x over previous
#include <cuda_runtime.h>
#include <math.h>

#define G   4096
#define NN  64
#define EE  256
#define FF  64
#define DD  128
#define EPN 32768
#define SHS 132   // padded row stride for sh (bank-conflict-free head reads)

// ---------------- device scratch (static, no allocations) ----------------
__device__ float d_gembs[G * DD];
__device__ float d_deg[G];
__device__ float d_agg1[G * DD];
__device__ float d_h[G * 256];
__device__ float d_agg2[G * 256];
__device__ float d_mu[G * DD];
__device__ float d_ls[G * DD];
__device__ float d_zc[G * 256];
__device__ float d_zl1[G * 256];
__device__ float d_zl2[G * 256];
__device__ float d_sums[8];   // 0:pen 1:plog 2:nlog 3:kl

// ---------------- zero scratch accumulators ----------------
__global__ void k_zero() {
    int i = blockIdx.x * blockDim.x + threadIdx.x;
    int stride = gridDim.x * blockDim.x;
    for (int j = i; j < G * 256; j += stride) d_agg2[j] = 0.f;
    for (int j = i; j < G * DD; j += stride) d_agg1[j] = 0.f;
    for (int j = i; j < G; j += stride) d_deg[j] = 0.f;
    if (i < 8) d_sums[i] = 0.f;
}

// ---------------- per-graph kernel: GCN + pooling head ----------------
// 256 threads; thread t -> (channel c = t&127, node-half = t>>7, 32 nodes each).
// dynamic smem: sh[64*SHS] (sx aliases front) | sxw[64*128] (sa1/sWf1 alias after agg)
__global__ void __launch_bounds__(256, 2) k_graph(
    const float* __restrict__ x, const int* __restrict__ ei, const float* __restrict__ ew,
    const float* __restrict__ Wg, const float* __restrict__ bg,
    const float* __restrict__ Wf1, const float* __restrict__ bf1,
    const float* __restrict__ Wf2, const float* __restrict__ bf2)
{
    extern __shared__ float sm[];
    float* sh   = sm;                    // 64*SHS floats
    float* sx   = sm;                    // 4096 floats (alias, dead after GEMM)
    float* sxw  = sm + NN * SHS;         // 8192 floats
    float* sa1  = sxw;                   // alias (after aggregation)
    float* sWf1 = sxw + 1024;            // alias (after aggregation) 2048 floats

    __shared__ int   ssrc[EE], sdst[EE], esrc[EE];
    __shared__ float swt[EE], enorm[EE];
    __shared__ float sdeg[NN], sdeg2[NN], sdinv[NN], sdinv2[NN];
    __shared__ int   scnt[NN], sstart[NN + 1], spos[NN];
    __shared__ float sS[NN * 2];
    __shared__ float sgpart[DD];
    __shared__ float sred[32];

    int g = blockIdx.x, t = threadIdx.x;
    int c = t & 127, half = t >> 7;

    // load x tile (64x64) and edges (1 edge/thread)
    const float4* xg = (const float4*)(x + (size_t)g * NN * FF);
    float4* sx4 = (float4*)sx;
    for (int i = t; i < NN * FF / 4; i += 256) sx4[i] = xg[i];
    int   es = ei[(size_t)g * 2 * EE + t];
    int   ed = ei[(size_t)g * 2 * EE + EE + t];
    float w  = ew[(size_t)g * EE + t];
    ssrc[t] = es; sdst[t] = ed; swt[t] = w;
    if (t < NN) { sdeg[t] = 0.f; sdeg2[t] = 0.f; scnt[t] = 0; }
    __syncthreads();

    atomicAdd(&sdeg[ed], w);     // GCN degree (at dst)
    atomicAdd(&sdeg2[es], w);    // Laplacian degree (at src)
    atomicAdd(&scnt[ed], 1);     // CSR counts
    __syncthreads();

    if (t < NN) {
        sdinv[t] = rsqrtf(sdeg[t] + 1.0f);
        float d2 = sdeg2[t];
        sdinv2[t] = (d2 > 0.f) ? rsqrtf(fmaxf(d2, 1e-30f)) : 0.f;
    }
    if (t == 0) {
        int s = 0;
        for (int n = 0; n < NN; n++) { sstart[n] = s; s += scnt[n]; }
        sstart[NN] = s;
    }
    __syncthreads();
    if (t < NN) spos[t] = sstart[t];
    __syncthreads();
    {   // CSR fill: slot per edge, sorted by dst
        int p = atomicAdd(&spos[ed], 1);
        esrc[p]  = es;
        enorm[p] = sdinv[es] * w * sdinv[ed];
    }

    // GEMM: xw = x @ W_gcn1 ; thread (c, half) owns 32-node strip of column c.
    // sx reads are warp-uniform (broadcast); Wg reads coalesced.
    float acc[32];
#pragma unroll
    for (int n = 0; n < 32; n++) acc[n] = 0.f;
    const float* sxh = sx + half * 32 * FF;
    for (int k = 0; k < FF; k += 4) {
        float w0 = Wg[(k + 0) * DD + c];
        float w1 = Wg[(k + 1) * DD + c];
        float w2 = Wg[(k + 2) * DD + c];
        float w3 = Wg[(k + 3) * DD + c];
#pragma unroll
        for (int n = 0; n < 32; n++) {
            float4 xv = *(const float4*)&sxh[n * FF + k];
            acc[n] = fmaf(xv.x, w0, fmaf(xv.y, w1, fmaf(xv.z, w2, fmaf(xv.w, w3, acc[n]))));
        }
    }
#pragma unroll
    for (int n = 0; n < 32; n++) sxw[(half * 32 + n) * DD + c] = acc[n];
    __syncthreads();

    // Aggregate via CSR (parallel over (node, channel)); fuse h and g_emb partial.
    float bias = bg[c];
    float gsum = 0.f;
#pragma unroll
    for (int n = 0; n < 32; n++) {
        int gn = half * 32 + n;
        float a2 = 0.f;
        int e0 = sstart[gn], e1 = sstart[gn + 1];
        for (int e = e0; e < e1; e++)            // esrc/enorm warp-uniform -> broadcast
            a2 = fmaf(sxw[esrc[e] * DD + c], enorm[e], a2);
        float di = sdinv[gn];
        float hv = a2 + acc[n] * di * di + bias;
        sh[gn * SHS + c] = hv;
        gsum += hv;
    }
    if (half == 1) sgpart[c] = gsum;
    __syncthreads();   // sxw dead after this point
    if (half == 0) d_gembs[(size_t)g * DD + c] = 0.5f * (gsum + sgpart[c]);

    // stage Wf1 into smem (aliases sxw)
    for (int i = t; i < DD * 16; i += 256) sWf1[i] = Wf1[i];
    __syncthreads();

    // a1 = tanh(h @ Wf1 + bf1) : 64x16 ; thread -> node t>>2, 4 j's
    {
        int n = t >> 2, j0 = (t & 3) * 4;
        float s0 = bf1[j0], s1 = bf1[j0 + 1], s2 = bf1[j0 + 2], s3 = bf1[j0 + 3];
        const float* shr = &sh[n * SHS];
        for (int d4 = 0; d4 < 32; d4++) {
            float4 hv = *(const float4*)&shr[d4 * 4];
            const float* wr0 = &sWf1[(d4 * 4 + 0) * 16 + j0];
            const float* wr1 = &sWf1[(d4 * 4 + 1) * 16 + j0];
            const float* wr2 = &sWf1[(d4 * 4 + 2) * 16 + j0];
            const float* wr3 = &sWf1[(d4 * 4 + 3) * 16 + j0];
            s0 = fmaf(hv.x, wr0[0], fmaf(hv.y, wr1[0], fmaf(hv.z, wr2[0], fmaf(hv.w, wr3[0], s0))));
            s1 = fmaf(hv.x, wr0[1], fmaf(hv.y, wr1[1], fmaf(hv.z, wr2[1], fmaf(hv.w, wr3[1], s1))));
            s2 = fmaf(hv.x, wr0[2], fmaf(hv.y, wr1[2], fmaf(hv.z, wr2[2], fmaf(hv.w, wr3[2], s2))));
            s3 = fmaf(hv.x, wr0[3], fmaf(hv.y, wr1[3], fmaf(hv.z, wr2[3], fmaf(hv.w, wr3[3], s3))));
        }
        sa1[n * 16 + j0 + 0] = tanhf(s0);
        sa1[n * 16 + j0 + 1] = tanhf(s1);
        sa1[n * 16 + j0 + 2] = tanhf(s2);
        sa1[n * 16 + j0 + 3] = tanhf(s3);
    }
    __syncthreads();

    // S = softmax(a1 @ Wf2 + bf2) : 64x2
    if (t < NN) {
        float l0 = bf2[0], l1 = bf2[1];
#pragma unroll
        for (int j = 0; j < 16; j++) {
            float a = sa1[t * 16 + j];
            l0 = fmaf(a, Wf2[j * 2], l0);
            l1 = fmaf(a, Wf2[j * 2 + 1], l1);
        }
        float m = fmaxf(l0, l1);
        float e0 = expf(l0 - m), e1 = expf(l1 - m);
        float inv = 1.f / (e0 + e1);
        sS[t * 2] = e0 * inv; sS[t * 2 + 1] = e1 * inv;
    }
    __syncthreads();

    // new_adj = S^T S + sum_e lw * outer(S[src], S[dst]) ; penalty
    float a00 = 0, a01 = 0, a10 = 0, a11 = 0;
    if (t < NN) {
        float s0 = sS[t * 2], s1 = sS[t * 2 + 1];
        a00 = s0 * s0; a01 = s0 * s1; a10 = s1 * s0; a11 = s1 * s1;
    }
    {
        float lw = -sdinv2[es] * w * sdinv2[ed];
        float p0 = sS[es * 2], p1 = sS[es * 2 + 1];
        float q0 = sS[ed * 2], q1 = sS[ed * 2 + 1];
        a00 = fmaf(lw, p0 * q0, a00); a01 = fmaf(lw, p0 * q1, a01);
        a10 = fmaf(lw, p1 * q0, a10); a11 = fmaf(lw, p1 * q1, a11);
    }
    for (int off = 16; off; off >>= 1) {
        a00 += __shfl_down_sync(0xffffffffu, a00, off);
        a01 += __shfl_down_sync(0xffffffffu, a01, off);
        a10 += __shfl_down_sync(0xffffffffu, a10, off);
        a11 += __shfl_down_sync(0xffffffffu, a11, off);
    }
    if ((t & 31) == 0) {
        int wi = t >> 5;
        sred[wi * 4 + 0] = a00; sred[wi * 4 + 1] = a01;
        sred[wi * 4 + 2] = a10; sred[wi * 4 + 3] = a11;
    }
    __syncthreads();
    if (t == 0) {
        float A00 = 0, A01 = 0, A10 = 0, A11 = 0;
        for (int wi = 0; wi < 8; wi++) {
            A00 += sred[wi * 4 + 0]; A01 += sred[wi * 4 + 1];
            A10 += sred[wi * 4 + 2]; A11 += sred[wi * 4 + 3];
        }
        float r0 = fmaxf(fabsf(A00) + fabsf(A01), 1e-12f);
        float r1 = fmaxf(fabsf(A10) + fabsf(A11), 1e-12f);
        float d0 = A00 / r0 - 1.f, d1 = A11 / r1 - 1.f;
        atomicAdd(&d_sums[0], 0.5f * (d0 * d0 + d1 * d1));
    }
}

// ---------------- graph-level degree ----------------
__global__ void k_deg(const int* __restrict__ pe) {
    int i = blockIdx.x * blockDim.x + threadIdx.x;
    if (i < EPN) atomicAdd(&d_deg[pe[EPN + i]], 1.0f);
}
__global__ void k_dinv() {
    int i = blockIdx.x * blockDim.x + threadIdx.x;
    if (i < G) d_deg[i] = rsqrtf(d_deg[i] + 1.0f);  // deg + self-loop
}

// ---------------- scatter (warp/edge) with fused self-loop term ----------------
__global__ void __launch_bounds__(256) k_scatter(const int* __restrict__ pe, int sel) {
    int tid = blockIdx.x * 256 + threadIdx.x;   // 0 .. EPN*32-1 (== 1M)
    int gw = tid >> 5, lane = tid & 31;
    int a = pe[gw], b = pe[EPN + gw];
    float norm = d_deg[a] * d_deg[b];
    if (sel == 0) {
        const float* X = d_gembs + (size_t)a * DD;
        float* Ag = d_agg1 + (size_t)b * DD;
#pragma unroll
        for (int d = lane; d < DD; d += 32) atomicAdd(&Ag[d], X[d] * norm);
        if (tid < G * DD) {
            float di = d_deg[tid >> 7];
            atomicAdd(&d_agg1[tid], d_gembs[tid] * di * di);
        }
    } else {
        const float* X = d_h + (size_t)a * 256;
        float* Ag = d_agg2 + (size_t)b * 256;
#pragma unroll
        for (int d = lane; d < 256; d += 32) atomicAdd(&Ag[d], X[d] * norm);
        float di = d_deg[tid >> 8];           // tid < G*256 exactly
        atomicAdd(&d_agg2[tid], d_h[tid] * di * di);
    }
}

// ---------------- tiled GEMM: C = act(A @ W + b), two-output fused ----------------
// BM=128, BN=64, BK=16, 256 threads, 8x4 micro-tile.
// sel_in: 0 agg1 / 1 agg2 / 2 zc.  sel_out: 0 -> d_h ; 1 -> mu|ls ; 2 -> zl1|zl2.
// Column space is [0, 2*Nsplit) conceptually; blocks with colBase >= Nsplit use W1/b1/act1.
__global__ void __launch_bounds__(256) k_gemm(
    int sel_in, int sel_out, int K, int Nsplit,
    const float* __restrict__ W0, const float* __restrict__ b0,
    const float* __restrict__ W1, const float* __restrict__ b1,
    int act0, int act1)
{
    const float* A = (sel_in == 0) ? d_agg1 : (sel_in == 1) ? d_agg2 : d_zc;
    int cg0 = blockIdx.x * 64;
    int hsel = (cg0 >= Nsplit);
    const float* W    = hsel ? W1 : W0;
    const float* bias = hsel ? b1 : b0;
    int act = hsel ? act1 : act0;
    int colBase = cg0 - (hsel ? Nsplit : 0);
    float* C;
    if (sel_out == 0) C = d_h;
    else if (sel_out == 1) C = hsel ? d_ls : d_mu;
    else C = hsel ? d_zl2 : d_zl1;
    int Cs = (sel_out == 1) ? DD : 256;

    __shared__ float As[16][132];
    __shared__ float Bs[16][68];
    int tid = threadIdx.x;
    int tx = tid & 15, ty = tid >> 4;
    int rowBase = blockIdx.y * 128;
    float accr[8][4];
#pragma unroll
    for (int i = 0; i < 8; i++)
#pragma unroll
        for (int j = 0; j < 4; j++) accr[i][j] = 0.f;

    int alm = tid >> 2, alk = (tid & 3) * 4;
    int blk = tid >> 4, bln = (tid & 15) * 4;

    for (int k0 = 0; k0 < K; k0 += 16) {
        float4 av0 = *(const float4*)&A[(size_t)(rowBase + alm) * K + k0 + alk];
        float4 av1 = *(const float4*)&A[(size_t)(rowBase + alm + 64) * K + k0 + alk];
        float4 wv  = *(const float4*)&W[(size_t)(k0 + blk) * Nsplit + colBase + bln];
        As[alk + 0][alm] = av0.x; As[alk + 1][alm] = av0.y;
        As[alk + 2][alm] = av0.z; As[alk + 3][alm] = av0.w;
        As[alk + 0][alm + 64] = av1.x; As[alk + 1][alm + 64] = av1.y;
        As[alk + 2][alm + 64] = av1.z; As[alk + 3][alm + 64] = av1.w;
        Bs[blk][bln + 0] = wv.x; Bs[blk][bln + 1] = wv.y;
        Bs[blk][bln + 2] = wv.z; Bs[blk][bln + 3] = wv.w;
        __syncthreads();
#pragma unroll
        for (int kk = 0; kk < 16; kk++) {
            float4 aa0 = *(const float4*)&As[kk][ty * 8];
            float4 aa1 = *(const float4*)&As[kk][ty * 8 + 4];
            float4 bb  = *(const float4*)&Bs[kk][tx * 4];
            float av[8] = {aa0.x, aa0.y, aa0.z, aa0.w, aa1.x, aa1.y, aa1.z, aa1.w};
            float bv[4] = {bb.x, bb.y, bb.z, bb.w};
#pragma unroll
            for (int i = 0; i < 8; i++)
#pragma unroll
                for (int j = 0; j < 4; j++) accr[i][j] = fmaf(av[i], bv[j], accr[i][j]);
        }
        __syncthreads();
    }
#pragma unroll
    for (int i = 0; i < 8; i++) {
        int r = rowBase + ty * 8 + i;
        int cc = colBase + tx * 4;
        float4 v;
        v.x = accr[i][0] + bias[cc + 0];
        v.y = accr[i][1] + bias[cc + 1];
        v.z = accr[i][2] + bias[cc + 2];
        v.w = accr[i][3] + bias[cc + 3];
        if (act == 1) { v.x = fmaxf(v.x, 0.f); v.y = fmaxf(v.y, 0.f); v.z = fmaxf(v.z, 0.f); v.w = fmaxf(v.w, 0.f); }
        else if (act == 2) { v.x = fminf(v.x, 10.f); v.y = fminf(v.y, 10.f); v.z = fminf(v.z, 10.f); v.w = fminf(v.w, 10.f); }
        *(float4*)&C[(size_t)r * Cs + cc] = v;
    }
}

// ---------------- z, zc, KL ----------------
__global__ void __launch_bounds__(256) k_z(const float* __restrict__ eps_,
                                           const float* __restrict__ emb) {
    int i = blockIdx.x * 256 + threadIdx.x;   // i < G*128 exactly
    float m = d_mu[i], l = d_ls[i];
    int n = i >> 7, d = i & 127;
    float z = m + eps_[i] * expf(l);
    d_zc[(size_t)n * 256 + d] = emb[i];
    d_zc[(size_t)n * 256 + 128 + d] = z;
    float klt = 1.f + 2.f * l - m * m - expf(2.f * l);
    for (int off = 16; off; off >>= 1) klt += __shfl_down_sync(0xffffffffu, klt, off);
    __shared__ float sw[8];
    if ((threadIdx.x & 31) == 0) sw[threadIdx.x >> 5] = klt;
    __syncthreads();
    if (threadIdx.x == 0) {
        float s = 0;
        for (int j = 0; j < 8; j++) s += sw[j];
        atomicAdd(&d_sums[3], s);
    }
}

// ---------------- edge predictions + log sums ----------------
__global__ void __launch_bounds__(256) k_pred(const int* __restrict__ pe,
                                              const int* __restrict__ ne,
                                              float* __restrict__ out) {
    int gw = (blockIdx.x * 256 + threadIdx.x) >> 5;
    int lane = threadIdx.x & 31;
    int wib = threadIdx.x >> 5;
    bool isneg = gw >= EPN;
    int i = isneg ? gw - EPN : gw;
    const int* e = isneg ? ne : pe;
    int a = e[i], b = e[EPN + i];
    const float4* ra = (const float4*)(d_zl1 + (size_t)a * 256);
    const float4* rb = (const float4*)(d_zl2 + (size_t)b * 256);
    float s = 0.f;
#pragma unroll
    for (int q = 0; q < 2; q++) {
        float4 u = ra[lane + 32 * q], v = rb[lane + 32 * q];
        s += u.x * v.x + u.y * v.y + u.z * v.z + u.w * v.w;
    }
    for (int off = 16; off; off >>= 1) s += __shfl_down_sync(0xffffffffu, s, off);
    __shared__ float sl[8];
    if (lane == 0) {
        float p = 1.f / (1.f + expf(-s));
        out[2 + gw] = p;
        sl[wib] = isneg ? logf(1.f - p + 1e-15f) : logf(p + 1e-15f);
    }
    __syncthreads();
    if (threadIdx.x == 0) {
        float tt = 0;
        for (int j = 0; j < 8; j++) tt += sl[j];
        atomicAdd(isneg ? &d_sums[2] : &d_sums[1], tt);
    }
}

__global__ void k_final(float* __restrict__ out) {
    float rec = -(d_sums[1] / (float)EPN) - (d_sums[2] / (float)EPN);
    float kl = -0.5f * d_sums[3] / (float)G;
    out[0] = rec + kl / (float)G;
    out[1] = d_sums[0] / (float)G;
}

// ---------------- launch ----------------
extern "C" void kernel_launch(void* const* d_in, const int* in_sizes, int n_in,
                              void* d_out, int out_size) {
    const float* x   = (const float*)d_in[0];
    const int*   ei  = (const int*)d_in[1];
    const float* ew  = (const float*)d_in[2];
    const int*   pe  = (const int*)d_in[3];
    const int*   ne  = (const int*)d_in[4];
    const float* eps_= (const float*)d_in[5];
    const float* Wg  = (const float*)d_in[6];
    const float* bg  = (const float*)d_in[7];
    const float* Wf1 = (const float*)d_in[8];
    const float* bf1 = (const float*)d_in[9];
    const float* Wf2 = (const float*)d_in[10];
    const float* bf2 = (const float*)d_in[11];
    const float* Wc1 = (const float*)d_in[12];
    const float* bc1 = (const float*)d_in[13];
    const float* Wmu = (const float*)d_in[14];
    const float* bmu = (const float*)d_in[15];
    const float* Wls = (const float*)d_in[16];
    const float* bls = (const float*)d_in[17];
    const float* emb = (const float*)d_in[18];
    const float* Wl1 = (const float*)d_in[19];
    const float* bl1 = (const float*)d_in[20];
    const float* Wl2 = (const float*)d_in[21];
    const float* bl2 = (const float*)d_in[22];
    float* out = (float*)d_out;

    const int dynsmem = (NN * SHS + NN * DD) * 4;   // sh + sxw
    cudaFuncSetAttribute(k_graph, cudaFuncAttributeMaxDynamicSharedMemorySize, dynsmem);

    k_zero<<<1024, 256>>>();
    k_graph<<<G, 256, dynsmem>>>(x, ei, ew, Wg, bg, Wf1, bf1, Wf2, bf2);
    k_deg<<<EPN / 256, 256>>>(pe);
    k_dinv<<<G / 256, 256>>>();
    k_scatter<<<EPN * 32 / 256, 256>>>(pe, 0);
    k_gemm<<<dim3(4, 32), 256>>>(0, 0, 128, 256, Wc1, bc1, Wc1, bc1, 1, 1);   // h = relu(agg1@Wc1+b)
    k_scatter<<<EPN * 32 / 256, 256>>>(pe, 1);
    k_gemm<<<dim3(4, 32), 256>>>(1, 1, 256, 128, Wmu, bmu, Wls, bls, 0, 2);   // mu | ls(min10)
    k_z<<<G * DD / 256, 256>>>(eps_, emb);
    k_gemm<<<dim3(8, 32), 256>>>(2, 2, 256, 256, Wl1, bl1, Wl2, bl2, 0, 0);   // zl1 | zl2
    k_pred<<<2 * EPN * 32 / 256, 256>>>(pe, ne, out);
    k_final<<<1, 1>>>(out);
}

// round 4
// speedup vs baseline: 1.5480x; 1.1188x over previous
#include <cuda_runtime.h>
#include <cuda_bf16.h>
#include <math.h>
#include <stdint.h>

#define G   4096
#define NN  64
#define EE  256
#define FF  64
#define DD  128
#define EPN 32768
#define SHS 132

// ---------------- device scratch (static, no allocations) ----------------
__device__ float d_xw[(size_t)G * NN * DD];   // 134 MB: x @ W_gcn1 for all graphs
__device__ float d_gembs[G * DD];
__device__ float d_deg[G];
__device__ float d_agg1[G * DD];
__device__ float d_h[G * 256];
__device__ float d_agg2[G * 256];
__device__ float d_mu[G * DD];
__device__ float d_ls[G * DD];
__device__ float d_zc[G * 256];
__device__ float d_zl1[G * 256];
__device__ float d_zl2[G * 256];
__device__ float d_sums[8];   // 0:pen 1:plog 2:nlog 3:kl
// transposed bf16 hi/lo weights [N][K]: Wg[0,8192) Wc1[8192,40960) Wmu[40960,73728)
// Wls[73728,106496) Wl1[106496,172032) Wl2[172032,237568)
__device__ __nv_bfloat16 d_wth[237568];
__device__ __nv_bfloat16 d_wtl[237568];

// ---------------- helpers ----------------
__device__ __forceinline__ void mma_bf16(float* c, const uint32_t* a, const uint32_t* b) {
    asm volatile("mma.sync.aligned.m16n8k16.row.col.f32.bf16.bf16.f32 "
        "{%0,%1,%2,%3}, {%4,%5,%6,%7}, {%8,%9}, {%0,%1,%2,%3};"
        : "+f"(c[0]), "+f"(c[1]), "+f"(c[2]), "+f"(c[3])
        : "r"(a[0]), "r"(a[1]), "r"(a[2]), "r"(a[3]), "r"(b[0]), "r"(b[1]));
}
__device__ __forceinline__ void cvt_split2(float x, float y, uint32_t& hi, uint32_t& lo) {
    __nv_bfloat162 h = __floats2bfloat162_rn(x, y);
    float rx = x - __bfloat162float(h.x);
    float ry = y - __bfloat162float(h.y);
    __nv_bfloat162 l = __floats2bfloat162_rn(rx, ry);
    hi = *(uint32_t*)&h;
    lo = *(uint32_t*)&l;
}

// ---------------- zero scratch accumulators ----------------
__global__ void k_zero() {
    int i = blockIdx.x * blockDim.x + threadIdx.x;
    int stride = gridDim.x * blockDim.x;
    for (int j = i; j < G * 256; j += stride) d_agg2[j] = 0.f;
    for (int j = i; j < G * DD; j += stride) d_agg1[j] = 0.f;
    for (int j = i; j < G; j += stride) d_deg[j] = 0.f;
    if (i < 8) d_sums[i] = 0.f;
}

// ---------------- weight transpose + bf16 hi/lo split ----------------
__global__ void k_prepw(const float* __restrict__ W0, const float* __restrict__ W1,
                        const float* __restrict__ W2, const float* __restrict__ W3,
                        const float* __restrict__ W4, const float* __restrict__ W5) {
    const float* Ws[6] = {W0, W1, W2, W3, W4, W5};
    const int Ks[6] = {64, 128, 256, 256, 256, 256};
    const int Ns[6] = {128, 256, 128, 128, 256, 256};
    const int offs[7] = {0, 8192, 40960, 73728, 106496, 172032, 237568};
    int i = blockIdx.x * blockDim.x + threadIdx.x;
    if (i >= 237568) return;
    int s = 0;
    while (i >= offs[s + 1]) s++;
    int local = i - offs[s];
    int K = Ks[s], N = Ns[s];
    int n = local / K, k = local - n * K;
    float v = Ws[s][k * N + n];
    __nv_bfloat16 h = __float2bfloat16(v);
    d_wth[i] = h;
    d_wtl[i] = __float2bfloat16(v - __bfloat162float(h));
}

// ---------------- mma.sync GEMM: C[128-rowblk, 128-colblk] = act(A@W + b) ----------
// A fp32 [M x K] row-major; W pre-transposed bf16 hi/lo [N x K].
// bf16 two-term split: C = Ah*Bh + Ah*Bl + Al*Bh (fp32 accum).
// 8 warps as 2(M) x 4(N); warp tile 64x32; m16n8k16 fragments loaded via LDS.
__global__ void __launch_bounds__(256) k_mma(
    const float* __restrict__ Ax, int selA, int K, int wtoff,
    const float* __restrict__ bias, int selC, int Cs, int act)
{
    __shared__ __nv_bfloat16 sAh[128][40];
    __shared__ __nv_bfloat16 sAl[128][40];
    __shared__ __nv_bfloat16 sBh[128][40];
    __shared__ __nv_bfloat16 sBl[128][40];
    __shared__ float sbias[128];

    int t = threadIdx.x;
    const float* A = (selA == 0) ? Ax : (selA == 1) ? d_agg1 : (selA == 2) ? d_agg2 : d_zc;
    float* C = (selC == 0) ? d_xw : (selC == 1) ? d_h : (selC == 2) ? d_mu
             : (selC == 3) ? d_ls : (selC == 4) ? d_zl1 : d_zl2;
    int rowBase = blockIdx.y * 128, colBase = blockIdx.x * 128;
    if (t < 128) sbias[t] = bias ? bias[colBase + t] : 0.f;

    int lane = t & 31, warp = t >> 5;
    int warpM = warp >> 2, warpN = warp & 3;

    float acc[4][4][4];
#pragma unroll
    for (int mt = 0; mt < 4; mt++)
#pragma unroll
        for (int nt = 0; nt < 4; nt++)
#pragma unroll
            for (int j = 0; j < 4; j++) acc[mt][nt][j] = 0.f;

    int ldr = t >> 1;           // 0..127
    int ldc = (t & 1) * 16;     // 0 | 16

    for (int kc = 0; kc < K; kc += 32) {
        // A chunk: 128x32 fp32 -> bf16 hi/lo (16 elems/thread)
        const float* Ar = A + (size_t)(rowBase + ldr) * K + kc + ldc;
#pragma unroll
        for (int j = 0; j < 4; j++) {
            float4 v = *(const float4*)(Ar + j * 4);
            uint32_t h0, l0, h1, l1;
            cvt_split2(v.x, v.y, h0, l0);
            cvt_split2(v.z, v.w, h1, l1);
            *(uint32_t*)&sAh[ldr][ldc + j * 4]     = h0;
            *(uint32_t*)&sAh[ldr][ldc + j * 4 + 2] = h1;
            *(uint32_t*)&sAl[ldr][ldc + j * 4]     = l0;
            *(uint32_t*)&sAl[ldr][ldc + j * 4 + 2] = l1;
        }
        // B chunk: copy 128x32 bf16 hi/lo (pre-transposed [N][K])
        {
            const __nv_bfloat16* bh = d_wth + wtoff + (size_t)(colBase + ldr) * K + kc + ldc;
            const __nv_bfloat16* bl = d_wtl + wtoff + (size_t)(colBase + ldr) * K + kc + ldc;
            *(uint4*)&sBh[ldr][ldc]     = *(const uint4*)bh;
            *(uint4*)&sBh[ldr][ldc + 8] = *(const uint4*)(bh + 8);
            *(uint4*)&sBl[ldr][ldc]     = *(const uint4*)bl;
            *(uint4*)&sBl[ldr][ldc + 8] = *(const uint4*)(bl + 8);
        }
        __syncthreads();

#pragma unroll
        for (int ks = 0; ks < 32; ks += 16) {
            int kb = ks + (lane & 3) * 2;
            int ar = warpM * 64 + (lane >> 2);
            uint32_t ah[4][4], al[4][4];
#pragma unroll
            for (int mt = 0; mt < 4; mt++) {
                int r = ar + mt * 16;
                ah[mt][0] = *(const uint32_t*)&sAh[r][kb];
                ah[mt][1] = *(const uint32_t*)&sAh[r + 8][kb];
                ah[mt][2] = *(const uint32_t*)&sAh[r][kb + 8];
                ah[mt][3] = *(const uint32_t*)&sAh[r + 8][kb + 8];
                al[mt][0] = *(const uint32_t*)&sAl[r][kb];
                al[mt][1] = *(const uint32_t*)&sAl[r + 8][kb];
                al[mt][2] = *(const uint32_t*)&sAl[r][kb + 8];
                al[mt][3] = *(const uint32_t*)&sAl[r + 8][kb + 8];
            }
            uint32_t bhf[4][2], blf[4][2];
#pragma unroll
            for (int nt = 0; nt < 4; nt++) {
                int r = warpN * 32 + nt * 8 + (lane >> 2);
                bhf[nt][0] = *(const uint32_t*)&sBh[r][kb];
                bhf[nt][1] = *(const uint32_t*)&sBh[r][kb + 8];
                blf[nt][0] = *(const uint32_t*)&sBl[r][kb];
                blf[nt][1] = *(const uint32_t*)&sBl[r][kb + 8];
            }
#pragma unroll
            for (int mt = 0; mt < 4; mt++)
#pragma unroll
                for (int nt = 0; nt < 4; nt++) {
                    mma_bf16(acc[mt][nt], ah[mt], bhf[nt]);
                    mma_bf16(acc[mt][nt], ah[mt], blf[nt]);
                    mma_bf16(acc[mt][nt], al[mt], bhf[nt]);
                }
        }
        __syncthreads();
    }

    // epilogue: fragments -> bias/act -> global (float2 stores)
#pragma unroll
    for (int mt = 0; mt < 4; mt++) {
        int r0 = rowBase + warpM * 64 + mt * 16 + (lane >> 2);
#pragma unroll
        for (int nt = 0; nt < 4; nt++) {
            int cl = warpN * 32 + nt * 8 + (lane & 3) * 2;
            float b0 = sbias[cl], b1 = sbias[cl + 1];
            float2 v0, v1;
            v0.x = acc[mt][nt][0] + b0; v0.y = acc[mt][nt][1] + b1;
            v1.x = acc[mt][nt][2] + b0; v1.y = acc[mt][nt][3] + b1;
            if (act == 1) {
                v0.x = fmaxf(v0.x, 0.f); v0.y = fmaxf(v0.y, 0.f);
                v1.x = fmaxf(v1.x, 0.f); v1.y = fmaxf(v1.y, 0.f);
            } else if (act == 2) {
                v0.x = fminf(v0.x, 10.f); v0.y = fminf(v0.y, 10.f);
                v1.x = fminf(v1.x, 10.f); v1.y = fminf(v1.y, 10.f);
            }
            *(float2*)&C[(size_t)r0 * Cs + colBase + cl] = v0;
            *(float2*)&C[(size_t)(r0 + 8) * Cs + colBase + cl] = v1;
        }
    }
}

// ---------------- per-graph kernel: aggregation + pooling head ----------------
__global__ void __launch_bounds__(256, 3) k_graph(
    const int* __restrict__ ei, const float* __restrict__ ew,
    const float* __restrict__ bg,
    const float* __restrict__ Wf1, const float* __restrict__ bf1,
    const float* __restrict__ Wf2, const float* __restrict__ bf2)
{
    extern __shared__ float sm[];
    float* sh   = sm;                    // 64*SHS
    float* sxw  = sm + NN * SHS;         // 8192
    float* sa1  = sxw;                   // alias (after aggregation)
    float* sWf1 = sxw + 1024;            // alias

    __shared__ int   ssrc[EE], sdst[EE], esrc[EE];
    __shared__ float swt[EE], enorm[EE];
    __shared__ float sdeg[NN], sdeg2[NN], sdinv[NN], sdinv2[NN];
    __shared__ int   scnt[NN], sstart[NN + 1], spos[NN];
    __shared__ float sS[NN * 2];
    __shared__ float sgpart[DD];
    __shared__ float sred[32];

    int g = blockIdx.x, t = threadIdx.x;
    int c = t & 127, half = t >> 7;

    const float4* xwg = (const float4*)(d_xw + (size_t)g * NN * DD);
    float4* sxw4 = (float4*)sxw;
    for (int i = t; i < NN * DD / 4; i += 256) sxw4[i] = xwg[i];
    int   es = ei[(size_t)g * 2 * EE + t];
    int   ed = ei[(size_t)g * 2 * EE + EE + t];
    float w  = ew[(size_t)g * EE + t];
    ssrc[t] = es; sdst[t] = ed; swt[t] = w;
    if (t < NN) { sdeg[t] = 0.f; sdeg2[t] = 0.f; scnt[t] = 0; }
    __syncthreads();

    atomicAdd(&sdeg[ed], w);
    atomicAdd(&sdeg2[es], w);
    atomicAdd(&scnt[ed], 1);
    __syncthreads();

    if (t < NN) {
        sdinv[t] = rsqrtf(sdeg[t] + 1.0f);
        float d2 = sdeg2[t];
        sdinv2[t] = (d2 > 0.f) ? rsqrtf(fmaxf(d2, 1e-30f)) : 0.f;
    }
    if (t == 0) {
        int s = 0;
        for (int n = 0; n < NN; n++) { sstart[n] = s; s += scnt[n]; }
        sstart[NN] = s;
    }
    __syncthreads();
    if (t < NN) spos[t] = sstart[t];
    __syncthreads();
    {
        int p = atomicAdd(&spos[ed], 1);
        esrc[p]  = es;
        enorm[p] = sdinv[es] * w * sdinv[ed];
    }
    __syncthreads();

    float bias = bg[c];
    float gsum = 0.f;
#pragma unroll
    for (int n = 0; n < 32; n++) {
        int gn = half * 32 + n;
        float a2 = 0.f;
        int e0 = sstart[gn], e1 = sstart[gn + 1];
        for (int e = e0; e < e1; e++)
            a2 = fmaf(sxw[esrc[e] * DD + c], enorm[e], a2);
        float di = sdinv[gn];
        float hv = a2 + sxw[gn * DD + c] * di * di + bias;
        sh[gn * SHS + c] = hv;
        gsum += hv;
    }
    if (half == 1) sgpart[c] = gsum;
    __syncthreads();   // sxw dead after this point
    if (half == 0) d_gembs[(size_t)g * DD + c] = 0.5f * (gsum + sgpart[c]);

    for (int i = t; i < DD * 16; i += 256) sWf1[i] = Wf1[i];
    __syncthreads();

    {
        int n = t >> 2, j0 = (t & 3) * 4;
        float s0 = bf1[j0], s1 = bf1[j0 + 1], s2 = bf1[j0 + 2], s3 = bf1[j0 + 3];
        const float* shr = &sh[n * SHS];
        for (int d4 = 0; d4 < 32; d4++) {
            float4 hv = *(const float4*)&shr[d4 * 4];
            const float* wr0 = &sWf1[(d4 * 4 + 0) * 16 + j0];
            const float* wr1 = &sWf1[(d4 * 4 + 1) * 16 + j0];
            const float* wr2 = &sWf1[(d4 * 4 + 2) * 16 + j0];
            const float* wr3 = &sWf1[(d4 * 4 + 3) * 16 + j0];
            s0 = fmaf(hv.x, wr0[0], fmaf(hv.y, wr1[0], fmaf(hv.z, wr2[0], fmaf(hv.w, wr3[0], s0))));
            s1 = fmaf(hv.x, wr0[1], fmaf(hv.y, wr1[1], fmaf(hv.z, wr2[1], fmaf(hv.w, wr3[1], s1))));
            s2 = fmaf(hv.x, wr0[2], fmaf(hv.y, wr1[2], fmaf(hv.z, wr2[2], fmaf(hv.w, wr3[2], s2))));
            s3 = fmaf(hv.x, wr0[3], fmaf(hv.y, wr1[3], fmaf(hv.z, wr2[3], fmaf(hv.w, wr3[3], s3))));
        }
        sa1[n * 16 + j0 + 0] = tanhf(s0);
        sa1[n * 16 + j0 + 1] = tanhf(s1);
        sa1[n * 16 + j0 + 2] = tanhf(s2);
        sa1[n * 16 + j0 + 3] = tanhf(s3);
    }
    __syncthreads();

    if (t < NN) {
        float l0 = bf2[0], l1 = bf2[1];
#pragma unroll
        for (int j = 0; j < 16; j++) {
            float a = sa1[t * 16 + j];
            l0 = fmaf(a, Wf2[j * 2], l0);
            l1 = fmaf(a, Wf2[j * 2 + 1], l1);
        }
        float m = fmaxf(l0, l1);
        float e0 = expf(l0 - m), e1 = expf(l1 - m);
        float inv = 1.f / (e0 + e1);
        sS[t * 2] = e0 * inv; sS[t * 2 + 1] = e1 * inv;
    }
    __syncthreads();

    float a00 = 0, a01 = 0, a10 = 0, a11 = 0;
    if (t < NN) {
        float s0 = sS[t * 2], s1 = sS[t * 2 + 1];
        a00 = s0 * s0; a01 = s0 * s1; a10 = s1 * s0; a11 = s1 * s1;
    }
    {
        float lw = -sdinv2[es] * w * sdinv2[ed];
        float p0 = sS[es * 2], p1 = sS[es * 2 + 1];
        float q0 = sS[ed * 2], q1 = sS[ed * 2 + 1];
        a00 = fmaf(lw, p0 * q0, a00); a01 = fmaf(lw, p0 * q1, a01);
        a10 = fmaf(lw, p1 * q0, a10); a11 = fmaf(lw, p1 * q1, a11);
    }
    for (int off = 16; off; off >>= 1) {
        a00 += __shfl_down_sync(0xffffffffu, a00, off);
        a01 += __shfl_down_sync(0xffffffffu, a01, off);
        a10 += __shfl_down_sync(0xffffffffu, a10, off);
        a11 += __shfl_down_sync(0xffffffffu, a11, off);
    }
    if ((t & 31) == 0) {
        int wi = t >> 5;
        sred[wi * 4 + 0] = a00; sred[wi * 4 + 1] = a01;
        sred[wi * 4 + 2] = a10; sred[wi * 4 + 3] = a11;
    }
    __syncthreads();
    if (t == 0) {
        float A00 = 0, A01 = 0, A10 = 0, A11 = 0;
        for (int wi = 0; wi < 8; wi++) {
            A00 += sred[wi * 4 + 0]; A01 += sred[wi * 4 + 1];
            A10 += sred[wi * 4 + 2]; A11 += sred[wi * 4 + 3];
        }
        float r0 = fmaxf(fabsf(A00) + fabsf(A01), 1e-12f);
        float r1 = fmaxf(fabsf(A10) + fabsf(A11), 1e-12f);
        float d0 = A00 / r0 - 1.f, d1 = A11 / r1 - 1.f;
        atomicAdd(&d_sums[0], 0.5f * (d0 * d0 + d1 * d1));
    }
}

// ---------------- graph-level degree ----------------
__global__ void k_deg(const int* __restrict__ pe) {
    int i = blockIdx.x * blockDim.x + threadIdx.x;
    if (i < EPN) atomicAdd(&d_deg[pe[EPN + i]], 1.0f);
}
__global__ void k_dinv() {
    int i = blockIdx.x * blockDim.x + threadIdx.x;
    if (i < G) d_deg[i] = rsqrtf(d_deg[i] + 1.0f);
}

// ---------------- scatter (warp/edge) with fused self-loop term ----------------
__global__ void __launch_bounds__(256) k_scatter(const int* __restrict__ pe, int sel) {
    int tid = blockIdx.x * 256 + threadIdx.x;   // 0 .. EPN*32-1
    int gw = tid >> 5, lane = tid & 31;
    int a = pe[gw], b = pe[EPN + gw];
    float norm = d_deg[a] * d_deg[b];
    if (sel == 0) {
        const float* X = d_gembs + (size_t)a * DD;
        float* Ag = d_agg1 + (size_t)b * DD;
#pragma unroll
        for (int d = lane; d < DD; d += 32) atomicAdd(&Ag[d], X[d] * norm);
        if (tid < G * DD) {
            float di = d_deg[tid >> 7];
            atomicAdd(&d_agg1[tid], d_gembs[tid] * di * di);
        }
    } else {
        const float* X = d_h + (size_t)a * 256;
        float* Ag = d_agg2 + (size_t)b * 256;
#pragma unroll
        for (int d = lane; d < 256; d += 32) atomicAdd(&Ag[d], X[d] * norm);
        float di = d_deg[tid >> 8];
        atomicAdd(&d_agg2[tid], d_h[tid] * di * di);
    }
}

// ---------------- z, zc, KL ----------------
__global__ void __launch_bounds__(256) k_z(const float* __restrict__ eps_,
                                           const float* __restrict__ emb) {
    int i = blockIdx.x * 256 + threadIdx.x;
    float m = d_mu[i], l = d_ls[i];
    int n = i >> 7, d = i & 127;
    float z = m + eps_[i] * expf(l);
    d_zc[(size_t)n * 256 + d] = emb[i];
    d_zc[(size_t)n * 256 + 128 + d] = z;
    float klt = 1.f + 2.f * l - m * m - expf(2.f * l);
    for (int off = 16; off; off >>= 1) klt += __shfl_down_sync(0xffffffffu, klt, off);
    __shared__ float sw[8];
    if ((threadIdx.x & 31) == 0) sw[threadIdx.x >> 5] = klt;
    __syncthreads();
    if (threadIdx.x == 0) {
        float s = 0;
        for (int j = 0; j < 8; j++) s += sw[j];
        atomicAdd(&d_sums[3], s);
    }
}

// ---------------- edge predictions + log sums ----------------
__global__ void __launch_bounds__(256) k_pred(const int* __restrict__ pe,
                                              const int* __restrict__ ne,
                                              float* __restrict__ out) {
    int gw = (blockIdx.x * 256 + threadIdx.x) >> 5;
    int lane = threadIdx.x & 31;
    int wib = threadIdx.x >> 5;
    bool isneg = gw >= EPN;
    int i = isneg ? gw - EPN : gw;
    const int* e = isneg ? ne : pe;
    int a = e[i], b = e[EPN + i];
    const float4* ra = (const float4*)(d_zl1 + (size_t)a * 256);
    const float4* rb = (const float4*)(d_zl2 + (size_t)b * 256);
    float s = 0.f;
#pragma unroll
    for (int q = 0; q < 2; q++) {
        float4 u = ra[lane + 32 * q], v = rb[lane + 32 * q];
        s += u.x * v.x + u.y * v.y + u.z * v.z + u.w * v.w;
    }
    for (int off = 16; off; off >>= 1) s += __shfl_down_sync(0xffffffffu, s, off);
    __shared__ float sl[8];
    if (lane == 0) {
        float p = 1.f / (1.f + expf(-s));
        out[2 + gw] = p;
        sl[wib] = isneg ? logf(1.f - p + 1e-15f) : logf(p + 1e-15f);
    }
    __syncthreads();
    if (threadIdx.x == 0) {
        float tt = 0;
        for (int j = 0; j < 8; j++) tt += sl[j];
        atomicAdd(isneg ? &d_sums[2] : &d_sums[1], tt);
    }
}

__global__ void k_final(float* __restrict__ out) {
    float rec = -(d_sums[1] / (float)EPN) - (d_sums[2] / (float)EPN);
    float kl = -0.5f * d_sums[3] / (float)G;
    out[0] = rec + kl / (float)G;
    out[1] = d_sums[0] / (float)G;
}

// ---------------- launch ----------------
extern "C" void kernel_launch(void* const* d_in, const int* in_sizes, int n_in,
                              void* d_out, int out_size) {
    const float* x   = (const float*)d_in[0];
    const int*   ei  = (const int*)d_in[1];
    const float* ew  = (const float*)d_in[2];
    const int*   pe  = (const int*)d_in[3];
    const int*   ne  = (const int*)d_in[4];
    const float* eps_= (const float*)d_in[5];
    const float* Wg  = (const float*)d_in[6];
    const float* bg  = (const float*)d_in[7];
    const float* Wf1 = (const float*)d_in[8];
    const float* bf1 = (const float*)d_in[9];
    const float* Wf2 = (const float*)d_in[10];
    const float* bf2 = (const float*)d_in[11];
    const float* Wc1 = (const float*)d_in[12];
    const float* bc1 = (const float*)d_in[13];
    const float* Wmu = (const float*)d_in[14];
    const float* bmu = (const float*)d_in[15];
    const float* Wls = (const float*)d_in[16];
    const float* bls = (const float*)d_in[17];
    const float* emb = (const float*)d_in[18];
    const float* Wl1 = (const float*)d_in[19];
    const float* bl1 = (const float*)d_in[20];
    const float* Wl2 = (const float*)d_in[21];
    const float* bl2 = (const float*)d_in[22];
    float* out = (float*)d_out;

    const int dyn_g = (NN * SHS + NN * DD) * 4;   // 66560
    cudaFuncSetAttribute(k_graph, cudaFuncAttributeMaxDynamicSharedMemorySize, dyn_g);

    k_zero<<<1024, 256>>>();
    k_prepw<<<232, 1024>>>(Wg, Wc1, Wmu, Wls, Wl1, Wl2);
    // xw = x @ Wg   [262144 x 64] @ [64 x 128]
    k_mma<<<dim3(1, 2048), 256>>>(x, 0, 64, 0, nullptr, 0, 128, 0);
    k_graph<<<G, 256, dyn_g>>>(ei, ew, bg, Wf1, bf1, Wf2, bf2);
    k_deg<<<EPN / 256, 256>>>(pe);
    k_dinv<<<G / 256, 256>>>();
    k_scatter<<<EPN * 32 / 256, 256>>>(pe, 0);
    // h = relu(agg1 @ Wc1 + bc1)   [4096x128]@[128x256]
    k_mma<<<dim3(2, 32), 256>>>(nullptr, 1, 128, 8192, bc1, 1, 256, 1);
    k_scatter<<<EPN * 32 / 256, 256>>>(pe, 1);
    // mu / logstd    [4096x256]@[256x128]
    k_mma<<<dim3(1, 32), 256>>>(nullptr, 2, 256, 40960, bmu, 2, 128, 0);
    k_mma<<<dim3(1, 32), 256>>>(nullptr, 2, 256, 73728, bls, 3, 128, 2);
    k_z<<<G * DD / 256, 256>>>(eps_, emb);
    // zl1 / zl2      [4096x256]@[256x256]
    k_mma<<<dim3(2, 32), 256>>>(nullptr, 3, 256, 106496, bl1, 4, 256, 0);
    k_mma<<<dim3(2, 32), 256>>>(nullptr, 3, 256, 172032, bl2, 5, 256, 0);
    k_pred<<<2 * EPN * 32 / 256, 256>>>(pe, ne, out);
    k_final<<<1, 1>>>(out);
}

// round 5
// speedup vs baseline: 1.6823x; 1.0868x over previous
#include <cuda_runtime.h>
#include <cuda_bf16.h>
#include <math.h>
#include <stdint.h>

#define G   4096
#define NN  64
#define EE  256
#define FF  64
#define DD  128
#define EPN 32768

// ---------------- device scratch (static, no allocations) ----------------
__device__ float d_hn[(size_t)G * NN * DD];   // 134 MB: per-node GCN output h
__device__ float d_a1[(size_t)G * NN * 16];   // 16.7 MB: tanh(h @ Wf1 + b)
__device__ float d_gembs[G * DD];
__device__ float d_deg[G];
__device__ float d_agg1[G * DD];
__device__ float d_h[G * 256];
__device__ float d_agg2[G * 256];
__device__ float d_mu[G * DD];
__device__ float d_ls[G * DD];
__device__ float d_zc[G * 256];
__device__ float d_zl1[G * 256];
__device__ float d_zl2[G * 256];
__device__ float d_sums[8];   // 0:pen 1:plog 2:nlog 3:kl
// transposed bf16 hi/lo weights [N][K]: Wg[0,8192) Wc1[8192,40960) Wmu[40960,73728)
// Wls[73728,106496) Wl1[106496,172032) Wl2[172032,237568) Wf1[237568,239616)
__device__ __nv_bfloat16 d_wth[239616];
__device__ __nv_bfloat16 d_wtl[239616];

// ---------------- helpers ----------------
__device__ __forceinline__ void mma_bf16(float* c, const uint32_t* a, const uint32_t* b) {
    asm volatile("mma.sync.aligned.m16n8k16.row.col.f32.bf16.bf16.f32 "
        "{%0,%1,%2,%3}, {%4,%5,%6,%7}, {%8,%9}, {%0,%1,%2,%3};"
        : "+f"(c[0]), "+f"(c[1]), "+f"(c[2]), "+f"(c[3])
        : "r"(a[0]), "r"(a[1]), "r"(a[2]), "r"(a[3]), "r"(b[0]), "r"(b[1]));
}
__device__ __forceinline__ void cvt_split2(float x, float y, uint32_t& hi, uint32_t& lo) {
    __nv_bfloat162 h = __floats2bfloat162_rn(x, y);
    float rx = x - __bfloat162float(h.x);
    float ry = y - __bfloat162float(h.y);
    __nv_bfloat162 l = __floats2bfloat162_rn(rx, ry);
    hi = *(uint32_t*)&h;
    lo = *(uint32_t*)&l;
}

// ---------------- zero scratch accumulators ----------------
__global__ void k_zero() {
    int i = blockIdx.x * blockDim.x + threadIdx.x;
    int stride = gridDim.x * blockDim.x;
    for (int j = i; j < G * 256; j += stride) d_agg2[j] = 0.f;
    for (int j = i; j < G * DD; j += stride) d_agg1[j] = 0.f;
    for (int j = i; j < G; j += stride) d_deg[j] = 0.f;
    if (i < 8) d_sums[i] = 0.f;
}

// ---------------- weight transpose + bf16 hi/lo split ----------------
__global__ void k_prepw(const float* __restrict__ W0, const float* __restrict__ W1,
                        const float* __restrict__ W2, const float* __restrict__ W3,
                        const float* __restrict__ W4, const float* __restrict__ W5,
                        const float* __restrict__ W6) {
    const float* Ws[7] = {W0, W1, W2, W3, W4, W5, W6};
    const int Ks[7] = {64, 128, 256, 256, 256, 256, 128};
    const int Ns[7] = {128, 256, 128, 128, 256, 256, 16};
    const int offs[8] = {0, 8192, 40960, 73728, 106496, 172032, 237568, 239616};
    int i = blockIdx.x * blockDim.x + threadIdx.x;
    if (i >= 239616) return;
    int s = 0;
    while (i >= offs[s + 1]) s++;
    int local = i - offs[s];
    int K = Ks[s], N = Ns[s];
    int n = local / K, k = local - n * K;
    float v = Ws[s][k * N + n];
    __nv_bfloat16 h = __float2bfloat16(v);
    d_wth[i] = h;
    d_wtl[i] = __float2bfloat16(v - __bfloat162float(h));
}

// ---------------- fused xw GEMM + GCN aggregation (2 graphs / block) ----------
// rows [blk*128, +128) = graphs 2b, 2b+1. HMMA-split x@Wg -> smem, CSR agg,
// h -> d_hn, g_emb -> d_gembs.
#define XST 132   // sxw row stride (floats)
__global__ void __launch_bounds__(256) k_xwagg(
    const float* __restrict__ x, const int* __restrict__ ei, const float* __restrict__ ew,
    const float* __restrict__ bg)
{
    extern __shared__ char dyn[];
    // union: stage sAh|sAl|sBh|sBl each [128][40] bf16 (40960 B)  vs  sxw [128][XST] f32
    __nv_bfloat16* sAh = (__nv_bfloat16*)dyn;
    __nv_bfloat16* sAl = sAh + 128 * 40;
    __nv_bfloat16* sBh = sAl + 128 * 40;
    __nv_bfloat16* sBl = sBh + 128 * 40;
    float* sxw = (float*)dyn;

    __shared__ int   esrc[512];
    __shared__ float enorm[512];
    __shared__ float sdeg[128], sdinv[128];
    __shared__ int   scnt[128], sstart[132], spos[128];

    int t = threadIdx.x, lane = t & 31, warp = t >> 5;
    int warpM = warp >> 2, warpN = warp & 3;
    size_t blockRow = (size_t)blockIdx.x * 128;
    const float* A = x + blockRow * 64;
    int g0 = blockIdx.x * 2;

    // ---- edges into registers (edge t of graph0 and graph1) ----
    int e_es[2], e_ed[2];
    float e_w[2];
#pragma unroll
    for (int j = 0; j < 2; j++) {
        e_es[j] = ei[(size_t)(g0 + j) * 512 + t];
        e_ed[j] = ei[(size_t)(g0 + j) * 512 + 256 + t];
        e_w[j]  = ew[(size_t)(g0 + j) * 256 + t];
    }
    if (t < 128) { sdeg[t] = 0.f; scnt[t] = 0; }
    __syncthreads();
#pragma unroll
    for (int j = 0; j < 2; j++) {
        atomicAdd(&sdeg[j * 64 + e_ed[j]], e_w[j]);
        atomicAdd(&scnt[j * 64 + e_ed[j]], 1);
    }
    __syncthreads();
    if (t < 128) sdinv[t] = rsqrtf(sdeg[t] + 1.0f);
    if (t < 2) {   // per-graph CSR prefix
        int s = t * 256;
        for (int n = 0; n < 64; n++) { sstart[t * 65 + n] = s; s += scnt[t * 64 + n]; }
        sstart[t * 65 + 64] = s;
    }
    __syncthreads();
    if (t < 128) spos[t] = sstart[(t >> 6) * 65 + (t & 63)];
    __syncthreads();
#pragma unroll
    for (int j = 0; j < 2; j++) {
        int p = atomicAdd(&spos[j * 64 + e_ed[j]], 1);
        esrc[p]  = j * 64 + e_es[j];    // row within 128-row tile
        enorm[p] = sdinv[j * 64 + e_es[j]] * e_w[j] * sdinv[j * 64 + e_ed[j]];
    }
    // (mma-loop __syncthreads below orders fill before aggregation)

    // ---- HMMA: xw = x @ Wg  (K=64, split bf16) ----
    float acc[4][4][4];
#pragma unroll
    for (int mt = 0; mt < 4; mt++)
#pragma unroll
        for (int nt = 0; nt < 4; nt++)
#pragma unroll
            for (int j = 0; j < 4; j++) acc[mt][nt][j] = 0.f;

    int ldr = t >> 1, ldc = (t & 1) * 16;
    for (int kc = 0; kc < 64; kc += 32) {
        const float* Ar = A + (size_t)ldr * 64 + kc + ldc;
#pragma unroll
        for (int j = 0; j < 4; j++) {
            float4 v = *(const float4*)(Ar + j * 4);
            uint32_t h0, l0, h1, l1;
            cvt_split2(v.x, v.y, h0, l0);
            cvt_split2(v.z, v.w, h1, l1);
            *(uint32_t*)&sAh[ldr * 40 + ldc + j * 4]     = h0;
            *(uint32_t*)&sAh[ldr * 40 + ldc + j * 4 + 2] = h1;
            *(uint32_t*)&sAl[ldr * 40 + ldc + j * 4]     = l0;
            *(uint32_t*)&sAl[ldr * 40 + ldc + j * 4 + 2] = l1;
        }
        {
            const __nv_bfloat16* bh = d_wth + (size_t)ldr * 64 + kc + ldc;
            const __nv_bfloat16* bl = d_wtl + (size_t)ldr * 64 + kc + ldc;
            *(uint4*)&sBh[ldr * 40 + ldc]     = *(const uint4*)bh;
            *(uint4*)&sBh[ldr * 40 + ldc + 8] = *(const uint4*)(bh + 8);
            *(uint4*)&sBl[ldr * 40 + ldc]     = *(const uint4*)bl;
            *(uint4*)&sBl[ldr * 40 + ldc + 8] = *(const uint4*)(bl + 8);
        }
        __syncthreads();
#pragma unroll
        for (int ks = 0; ks < 32; ks += 16) {
            int kb = ks + (lane & 3) * 2;
            int ar = warpM * 64 + (lane >> 2);
            uint32_t ah[4][4], al[4][4];
#pragma unroll
            for (int mt = 0; mt < 4; mt++) {
                int r = ar + mt * 16;
                ah[mt][0] = *(const uint32_t*)&sAh[r * 40 + kb];
                ah[mt][1] = *(const uint32_t*)&sAh[(r + 8) * 40 + kb];
                ah[mt][2] = *(const uint32_t*)&sAh[r * 40 + kb + 8];
                ah[mt][3] = *(const uint32_t*)&sAh[(r + 8) * 40 + kb + 8];
                al[mt][0] = *(const uint32_t*)&sAl[r * 40 + kb];
                al[mt][1] = *(const uint32_t*)&sAl[(r + 8) * 40 + kb];
                al[mt][2] = *(const uint32_t*)&sAl[r * 40 + kb + 8];
                al[mt][3] = *(const uint32_t*)&sAl[(r + 8) * 40 + kb + 8];
            }
            uint32_t bhf[4][2], blf[4][2];
#pragma unroll
            for (int nt = 0; nt < 4; nt++) {
                int r = warpN * 32 + nt * 8 + (lane >> 2);
                bhf[nt][0] = *(const uint32_t*)&sBh[r * 40 + kb];
                bhf[nt][1] = *(const uint32_t*)&sBh[r * 40 + kb + 8];
                blf[nt][0] = *(const uint32_t*)&sBl[r * 40 + kb];
                blf[nt][1] = *(const uint32_t*)&sBl[r * 40 + kb + 8];
            }
#pragma unroll
            for (int mt = 0; mt < 4; mt++)
#pragma unroll
                for (int nt = 0; nt < 4; nt++) {
                    mma_bf16(acc[mt][nt], ah[mt], bhf[nt]);
                    mma_bf16(acc[mt][nt], ah[mt], blf[nt]);
                    mma_bf16(acc[mt][nt], al[mt], bhf[nt]);
                }
        }
        __syncthreads();
    }

    // ---- park xw in smem ----
#pragma unroll
    for (int mt = 0; mt < 4; mt++) {
        int r0 = warpM * 64 + mt * 16 + (lane >> 2);
#pragma unroll
        for (int nt = 0; nt < 4; nt++) {
            int cl = warpN * 32 + nt * 8 + (lane & 3) * 2;
            float2 v0, v1;
            v0.x = acc[mt][nt][0]; v0.y = acc[mt][nt][1];
            v1.x = acc[mt][nt][2]; v1.y = acc[mt][nt][3];
            *(float2*)&sxw[r0 * XST + cl] = v0;
            *(float2*)&sxw[(r0 + 8) * XST + cl] = v1;
        }
    }
    __syncthreads();

    // ---- CSR aggregation: thread (gr = t>>7, c = t&127), all 64 nodes ----
    {
        int gr = t >> 7, c = t & 127;
        float bias = bg[c];
        float gsum = 0.f;
        float* out = d_hn + (blockRow + (size_t)gr * 64) * 128 + c;
#pragma unroll 4
        for (int n = 0; n < 64; n++) {
            float a2 = 0.f;
            int e0 = sstart[gr * 65 + n], e1 = sstart[gr * 65 + n + 1];
            for (int e = e0; e < e1; e++)
                a2 = fmaf(sxw[esrc[e] * XST + c], enorm[e], a2);
            float di = sdinv[gr * 64 + n];
            float hv = a2 + sxw[(gr * 64 + n) * XST + c] * di * di + bias;
            out[(size_t)n * 128] = hv;
            gsum += hv;
        }
        d_gembs[(size_t)(g0 + gr) * 128 + c] = 0.5f * gsum;
    }
}

// ---------------- a1 = tanh(d_hn @ Wf1 + bf1) : fragment-direct GEMM ----------
__global__ void __launch_bounds__(256) k_mma16(const float* __restrict__ bf1v) {
    int t = threadIdx.x, lane = t & 31, w = t >> 5;
    size_t rowBase = (size_t)blockIdx.x * 128 + w * 16;
    const float* Arow = d_hn + rowBase * 128;
    int r = lane >> 2, kb = (lane & 3) * 2;
    float acc[2][4];
#pragma unroll
    for (int nt = 0; nt < 2; nt++)
#pragma unroll
        for (int j = 0; j < 4; j++) acc[nt][j] = 0.f;
    const __nv_bfloat16* Bh = d_wth + 237568;
    const __nv_bfloat16* Bl = d_wtl + 237568;
#pragma unroll
    for (int ks = 0; ks < 8; ks++) {
        int k0 = ks * 16 + kb;
        float2 f0 = *(const float2*)(Arow + (size_t)r * 128 + k0);
        float2 f1 = *(const float2*)(Arow + (size_t)(r + 8) * 128 + k0);
        float2 f2 = *(const float2*)(Arow + (size_t)r * 128 + k0 + 8);
        float2 f3 = *(const float2*)(Arow + (size_t)(r + 8) * 128 + k0 + 8);
        uint32_t ah[4], al[4];
        cvt_split2(f0.x, f0.y, ah[0], al[0]);
        cvt_split2(f1.x, f1.y, ah[1], al[1]);
        cvt_split2(f2.x, f2.y, ah[2], al[2]);
        cvt_split2(f3.x, f3.y, ah[3], al[3]);
#pragma unroll
        for (int nt = 0; nt < 2; nt++) {
            int n = nt * 8 + r;
            uint32_t bh[2], bl[2];
            bh[0] = *(const uint32_t*)(Bh + n * 128 + ks * 16 + kb);
            bh[1] = *(const uint32_t*)(Bh + n * 128 + ks * 16 + kb + 8);
            bl[0] = *(const uint32_t*)(Bl + n * 128 + ks * 16 + kb);
            bl[1] = *(const uint32_t*)(Bl + n * 128 + ks * 16 + kb + 8);
            mma_bf16(acc[nt], ah, bh);
            mma_bf16(acc[nt], ah, bl);
            mma_bf16(acc[nt], al, bh);
        }
    }
#pragma unroll
    for (int nt = 0; nt < 2; nt++) {
        int c0 = nt * 8 + (lane & 3) * 2;
        float b0 = bf1v[c0], b1 = bf1v[c0 + 1];
        float2 v0, v1;
        v0.x = tanhf(acc[nt][0] + b0); v0.y = tanhf(acc[nt][1] + b1);
        v1.x = tanhf(acc[nt][2] + b0); v1.y = tanhf(acc[nt][3] + b1);
        *(float2*)(d_a1 + (rowBase + r) * 16 + c0) = v0;
        *(float2*)(d_a1 + (rowBase + r + 8) * 16 + c0) = v1;
    }
}

// ---------------- per-graph head: S softmax + Laplacian penalty ----------------
__global__ void __launch_bounds__(64) k_head(
    const int* __restrict__ ei, const float* __restrict__ ew,
    const float* __restrict__ Wf2, const float* __restrict__ bf2)
{
    __shared__ float sS[NN * 2];
    __shared__ float sdeg2[NN];
    __shared__ float sred[8];
    int g = blockIdx.x, t = threadIdx.x;

    // logits from a1 row
    const float4* a4 = (const float4*)(d_a1 + ((size_t)g * 64 + t) * 16);
    float l0 = bf2[0], l1 = bf2[1];
#pragma unroll
    for (int q = 0; q < 4; q++) {
        float4 a = a4[q];
        l0 = fmaf(a.x, Wf2[(q * 4 + 0) * 2], l0); l1 = fmaf(a.x, Wf2[(q * 4 + 0) * 2 + 1], l1);
        l0 = fmaf(a.y, Wf2[(q * 4 + 1) * 2], l0); l1 = fmaf(a.y, Wf2[(q * 4 + 1) * 2 + 1], l1);
        l0 = fmaf(a.z, Wf2[(q * 4 + 2) * 2], l0); l1 = fmaf(a.z, Wf2[(q * 4 + 2) * 2 + 1], l1);
        l0 = fmaf(a.w, Wf2[(q * 4 + 3) * 2], l0); l1 = fmaf(a.w, Wf2[(q * 4 + 3) * 2 + 1], l1);
    }
    float m = fmaxf(l0, l1);
    float e0 = expf(l0 - m), e1 = expf(l1 - m);
    float inv = 1.f / (e0 + e1);
    sS[t * 2] = e0 * inv; sS[t * 2 + 1] = e1 * inv;
    sdeg2[t] = 0.f;
    __syncthreads();

    // edges: 4 per thread; Laplacian degree at src
    int es[4], ed[4];
    float w[4];
#pragma unroll
    for (int j = 0; j < 4; j++) {
        int e = t * 4 + j;
        es[j] = ei[(size_t)g * 512 + e];
        ed[j] = ei[(size_t)g * 512 + 256 + e];
        w[j]  = ew[(size_t)g * 256 + e];
        atomicAdd(&sdeg2[es[j]], w[j]);
    }
    __syncthreads();
    float d2 = sdeg2[t];
    float di2 = (d2 > 0.f) ? rsqrtf(fmaxf(d2, 1e-30f)) : 0.f;
    __syncthreads();
    sdeg2[t] = di2;
    __syncthreads();

    float a00, a01, a10, a11;
    {
        float s0 = sS[t * 2], s1 = sS[t * 2 + 1];
        a00 = s0 * s0; a01 = s0 * s1; a10 = s1 * s0; a11 = s1 * s1;
    }
#pragma unroll
    for (int j = 0; j < 4; j++) {
        float lw = -sdeg2[es[j]] * w[j] * sdeg2[ed[j]];
        float p0 = sS[es[j] * 2], p1 = sS[es[j] * 2 + 1];
        float q0 = sS[ed[j] * 2], q1 = sS[ed[j] * 2 + 1];
        a00 = fmaf(lw, p0 * q0, a00); a01 = fmaf(lw, p0 * q1, a01);
        a10 = fmaf(lw, p1 * q0, a10); a11 = fmaf(lw, p1 * q1, a11);
    }
    for (int off = 16; off; off >>= 1) {
        a00 += __shfl_down_sync(0xffffffffu, a00, off);
        a01 += __shfl_down_sync(0xffffffffu, a01, off);
        a10 += __shfl_down_sync(0xffffffffu, a10, off);
        a11 += __shfl_down_sync(0xffffffffu, a11, off);
    }
    if ((t & 31) == 0) {
        int wi = t >> 5;
        sred[wi * 4 + 0] = a00; sred[wi * 4 + 1] = a01;
        sred[wi * 4 + 2] = a10; sred[wi * 4 + 3] = a11;
    }
    __syncthreads();
    if (t == 0) {
        float A00 = sred[0] + sred[4], A01 = sred[1] + sred[5];
        float A10 = sred[2] + sred[6], A11 = sred[3] + sred[7];
        float r0 = fmaxf(fabsf(A00) + fabsf(A01), 1e-12f);
        float r1 = fmaxf(fabsf(A10) + fabsf(A11), 1e-12f);
        float dd0 = A00 / r0 - 1.f, dd1 = A11 / r1 - 1.f;
        atomicAdd(&d_sums[0], 0.5f * (dd0 * dd0 + dd1 * dd1));
    }
}

// ---------------- mma.sync GEMM (graph-level): C = act(A @ W + b) --------------
__global__ void __launch_bounds__(256) k_mma(
    int selA, int K, int wtoff,
    const float* __restrict__ bias, int selC, int Cs, int act)
{
    __shared__ __nv_bfloat16 sAh[128][40];
    __shared__ __nv_bfloat16 sAl[128][40];
    __shared__ __nv_bfloat16 sBh[128][40];
    __shared__ __nv_bfloat16 sBl[128][40];
    __shared__ float sbias[128];

    int t = threadIdx.x;
    const float* A = (selA == 1) ? d_agg1 : (selA == 2) ? d_agg2 : d_zc;
    float* C = (selC == 1) ? d_h : (selC == 2) ? d_mu
             : (selC == 3) ? d_ls : (selC == 4) ? d_zl1 : d_zl2;
    int rowBase = blockIdx.y * 128, colBase = blockIdx.x * 128;
    if (t < 128) sbias[t] = bias[colBase + t];

    int lane = t & 31, warp = t >> 5;
    int warpM = warp >> 2, warpN = warp & 3;

    float acc[4][4][4];
#pragma unroll
    for (int mt = 0; mt < 4; mt++)
#pragma unroll
        for (int nt = 0; nt < 4; nt++)
#pragma unroll
            for (int j = 0; j < 4; j++) acc[mt][nt][j] = 0.f;

    int ldr = t >> 1, ldc = (t & 1) * 16;

    for (int kc = 0; kc < K; kc += 32) {
        const float* Ar = A + (size_t)(rowBase + ldr) * K + kc + ldc;
#pragma unroll
        for (int j = 0; j < 4; j++) {
            float4 v = *(const float4*)(Ar + j * 4);
            uint32_t h0, l0, h1, l1;
            cvt_split2(v.x, v.y, h0, l0);
            cvt_split2(v.z, v.w, h1, l1);
            *(uint32_t*)&sAh[ldr][ldc + j * 4]     = h0;
            *(uint32_t*)&sAh[ldr][ldc + j * 4 + 2] = h1;
            *(uint32_t*)&sAl[ldr][ldc + j * 4]     = l0;
            *(uint32_t*)&sAl[ldr][ldc + j * 4 + 2] = l1;
        }
        {
            const __nv_bfloat16* bh = d_wth + wtoff + (size_t)(colBase + ldr) * K + kc + ldc;
            const __nv_bfloat16* bl = d_wtl + wtoff + (size_t)(colBase + ldr) * K + kc + ldc;
            *(uint4*)&sBh[ldr][ldc]     = *(const uint4*)bh;
            *(uint4*)&sBh[ldr][ldc + 8] = *(const uint4*)(bh + 8);
            *(uint4*)&sBl[ldr][ldc]     = *(const uint4*)bl;
            *(uint4*)&sBl[ldr][ldc + 8] = *(const uint4*)(bl + 8);
        }
        __syncthreads();
#pragma unroll
        for (int ks = 0; ks < 32; ks += 16) {
            int kb = ks + (lane & 3) * 2;
            int ar = warpM * 64 + (lane >> 2);
            uint32_t ah[4][4], al[4][4];
#pragma unroll
            for (int mt = 0; mt < 4; mt++) {
                int r = ar + mt * 16;
                ah[mt][0] = *(const uint32_t*)&sAh[r][kb];
                ah[mt][1] = *(const uint32_t*)&sAh[r + 8][kb];
                ah[mt][2] = *(const uint32_t*)&sAh[r][kb + 8];
                ah[mt][3] = *(const uint32_t*)&sAh[r + 8][kb + 8];
                al[mt][0] = *(const uint32_t*)&sAl[r][kb];
                al[mt][1] = *(const uint32_t*)&sAl[r + 8][kb];
                al[mt][2] = *(const uint32_t*)&sAl[r][kb + 8];
                al[mt][3] = *(const uint32_t*)&sAl[r + 8][kb + 8];
            }
            uint32_t bhf[4][2], blf[4][2];
#pragma unroll
            for (int nt = 0; nt < 4; nt++) {
                int r = warpN * 32 + nt * 8 + (lane >> 2);
                bhf[nt][0] = *(const uint32_t*)&sBh[r][kb];
                bhf[nt][1] = *(const uint32_t*)&sBh[r][kb + 8];
                blf[nt][0] = *(const uint32_t*)&sBl[r][kb];
                blf[nt][1] = *(const uint32_t*)&sBl[r][kb + 8];
            }
#pragma unroll
            for (int mt = 0; mt < 4; mt++)
#pragma unroll
                for (int nt = 0; nt < 4; nt++) {
                    mma_bf16(acc[mt][nt], ah[mt], bhf[nt]);
                    mma_bf16(acc[mt][nt], ah[mt], blf[nt]);
                    mma_bf16(acc[mt][nt], al[mt], bhf[nt]);
                }
        }
        __syncthreads();
    }

#pragma unroll
    for (int mt = 0; mt < 4; mt++) {
        int r0 = rowBase + warpM * 64 + mt * 16 + (lane >> 2);
#pragma unroll
        for (int nt = 0; nt < 4; nt++) {
            int cl = warpN * 32 + nt * 8 + (lane & 3) * 2;
            float b0 = sbias[cl], b1 = sbias[cl + 1];
            float2 v0, v1;
            v0.x = acc[mt][nt][0] + b0; v0.y = acc[mt][nt][1] + b1;
            v1.x = acc[mt][nt][2] + b0; v1.y = acc[mt][nt][3] + b1;
            if (act == 1) {
                v0.x = fmaxf(v0.x, 0.f); v0.y = fmaxf(v0.y, 0.f);
                v1.x = fmaxf(v1.x, 0.f); v1.y = fmaxf(v1.y, 0.f);
            } else if (act == 2) {
                v0.x = fminf(v0.x, 10.f); v0.y = fminf(v0.y, 10.f);
                v1.x = fminf(v1.x, 10.f); v1.y = fminf(v1.y, 10.f);
            }
            *(float2*)&C[(size_t)r0 * Cs + colBase + cl] = v0;
            *(float2*)&C[(size_t)(r0 + 8) * Cs + colBase + cl] = v1;
        }
    }
}

// ---------------- graph-level degree ----------------
__global__ void k_deg(const int* __restrict__ pe) {
    int i = blockIdx.x * blockDim.x + threadIdx.x;
    if (i < EPN) atomicAdd(&d_deg[pe[EPN + i]], 1.0f);
}
__global__ void k_dinv() {
    int i = blockIdx.x * blockDim.x + threadIdx.x;
    if (i < G) d_deg[i] = rsqrtf(d_deg[i] + 1.0f);
}

// ---------------- scatter (warp/edge) with fused self-loop term ----------------
__global__ void __launch_bounds__(256) k_scatter(const int* __restrict__ pe, int sel) {
    int tid = blockIdx.x * 256 + threadIdx.x;   // 0 .. EPN*32-1
    int gw = tid >> 5, lane = tid & 31;
    int a = pe[gw], b = pe[EPN + gw];
    float norm = d_deg[a] * d_deg[b];
    if (sel == 0) {
        const float* X = d_gembs + (size_t)a * DD;
        float* Ag = d_agg1 + (size_t)b * DD;
#pragma unroll
        for (int d = lane; d < DD; d += 32) atomicAdd(&Ag[d], X[d] * norm);
        if (tid < G * DD) {
            float di = d_deg[tid >> 7];
            atomicAdd(&d_agg1[tid], d_gembs[tid] * di * di);
        }
    } else {
        const float* X = d_h + (size_t)a * 256;
        float* Ag = d_agg2 + (size_t)b * 256;
#pragma unroll
        for (int d = lane; d < 256; d += 32) atomicAdd(&Ag[d], X[d] * norm);
        float di = d_deg[tid >> 8];
        atomicAdd(&d_agg2[tid], d_h[tid] * di * di);
    }
}

// ---------------- z, zc, KL ----------------
__global__ void __launch_bounds__(256) k_z(const float* __restrict__ eps_,
                                           const float* __restrict__ emb) {
    int i = blockIdx.x * 256 + threadIdx.x;
    float m = d_mu[i], l = d_ls[i];
    int n = i >> 7, d = i & 127;
    float z = m + eps_[i] * expf(l);
    d_zc[(size_t)n * 256 + d] = emb[i];
    d_zc[(size_t)n * 256 + 128 + d] = z;
    float klt = 1.f + 2.f * l - m * m - expf(2.f * l);
    for (int off = 16; off; off >>= 1) klt += __shfl_down_sync(0xffffffffu, klt, off);
    __shared__ float sw[8];
    if ((threadIdx.x & 31) == 0) sw[threadIdx.x >> 5] = klt;
    __syncthreads();
    if (threadIdx.x == 0) {
        float s = 0;
        for (int j = 0; j < 8; j++) s += sw[j];
        atomicAdd(&d_sums[3], s);
    }
}

// ---------------- edge predictions + log sums ----------------
__global__ void __launch_bounds__(256) k_pred(const int* __restrict__ pe,
                                              const int* __restrict__ ne,
                                              float* __restrict__ out) {
    int gw = (blockIdx.x * 256 + threadIdx.x) >> 5;
    int lane = threadIdx.x & 31;
    int wib = threadIdx.x >> 5;
    bool isneg = gw >= EPN;
    int i = isneg ? gw - EPN : gw;
    const int* e = isneg ? ne : pe;
    int a = e[i], b = e[EPN + i];
    const float4* ra = (const float4*)(d_zl1 + (size_t)a * 256);
    const float4* rb = (const float4*)(d_zl2 + (size_t)b * 256);
    float s = 0.f;
#pragma unroll
    for (int q = 0; q < 2; q++) {
        float4 u = ra[lane + 32 * q], v = rb[lane + 32 * q];
        s += u.x * v.x + u.y * v.y + u.z * v.z + u.w * v.w;
    }
    for (int off = 16; off; off >>= 1) s += __shfl_down_sync(0xffffffffu, s, off);
    __shared__ float sl[8];
    if (lane == 0) {
        float p = 1.f / (1.f + expf(-s));
        out[2 + gw] = p;
        sl[wib] = isneg ? logf(1.f - p + 1e-15f) : logf(p + 1e-15f);
    }
    __syncthreads();
    if (threadIdx.x == 0) {
        float tt = 0;
        for (int j = 0; j < 8; j++) tt += sl[j];
        atomicAdd(isneg ? &d_sums[2] : &d_sums[1], tt);
    }
}

__global__ void k_final(float* __restrict__ out) {
    float rec = -(d_sums[1] / (float)EPN) - (d_sums[2] / (float)EPN);
    float kl = -0.5f * d_sums[3] / (float)G;
    out[0] = rec + kl / (float)G;
    out[1] = d_sums[0] / (float)G;
}

// ---------------- launch ----------------
extern "C" void kernel_launch(void* const* d_in, const int* in_sizes, int n_in,
                              void* d_out, int out_size) {
    const float* x   = (const float*)d_in[0];
    const int*   ei  = (const int*)d_in[1];
    const float* ew  = (const float*)d_in[2];
    const int*   pe  = (const int*)d_in[3];
    const int*   ne  = (const int*)d_in[4];
    const float* eps_= (const float*)d_in[5];
    const float* Wg  = (const float*)d_in[6];
    const float* bg  = (const float*)d_in[7];
    const float* Wf1 = (const float*)d_in[8];
    const float* bf1 = (const float*)d_in[9];
    const float* Wf2 = (const float*)d_in[10];
    const float* bf2 = (const float*)d_in[11];
    const float* Wc1 = (const float*)d_in[12];
    const float* bc1 = (const float*)d_in[13];
    const float* Wmu = (const float*)d_in[14];
    const float* bmu = (const float*)d_in[15];
    const float* Wls = (const float*)d_in[16];
    const float* bls = (const float*)d_in[17];
    const float* emb = (const float*)d_in[18];
    const float* Wl1 = (const float*)d_in[19];
    const float* bl1 = (const float*)d_in[20];
    const float* Wl2 = (const float*)d_in[21];
    const float* bl2 = (const float*)d_in[22];
    float* out = (float*)d_out;

    const int dyn_xw = 128 * XST * 4;   // 67584
    cudaFuncSetAttribute(k_xwagg, cudaFuncAttributeMaxDynamicSharedMemorySize, dyn_xw);

    k_zero<<<1024, 256>>>();
    k_prepw<<<234, 1024>>>(Wg, Wc1, Wmu, Wls, Wl1, Wl2, Wf1);
    k_xwagg<<<G / 2, 256, dyn_xw>>>(x, ei, ew, bg);
    k_mma16<<<G * NN / 128, 256>>>(bf1);
    k_head<<<G, 64>>>(ei, ew, Wf2, bf2);
    k_deg<<<EPN / 256, 256>>>(pe);
    k_dinv<<<G / 256, 256>>>();
    k_scatter<<<EPN * 32 / 256, 256>>>(pe, 0);
    // h = relu(agg1 @ Wc1 + bc1)   [4096x128]@[128x256]
    k_mma<<<dim3(2, 32), 256>>>(1, 128, 8192, bc1, 1, 256, 1);
    k_scatter<<<EPN * 32 / 256, 256>>>(pe, 1);
    // mu / logstd    [4096x256]@[256x128]
    k_mma<<<dim3(1, 32), 256>>>(2, 256, 40960, bmu, 2, 128, 0);
    k_mma<<<dim3(1, 32), 256>>>(2, 256, 73728, bls, 3, 128, 2);
    k_z<<<G * DD / 256, 256>>>(eps_, emb);
    // zl1 / zl2      [4096x256]@[256x256]
    k_mma<<<dim3(2, 32), 256>>>(3, 256, 106496, bl1, 4, 256, 0);
    k_mma<<<dim3(2, 32), 256>>>(3, 256, 172032, bl2, 5, 256, 0);
    k_pred<<<2 * EPN * 32 / 256, 256>>>(pe, ne, out);
    k_final<<<1, 1>>>(out);
}